// round 5
// baseline (speedup 1.0000x reference)
#include <cuda_runtime.h>
#include <cuda_bf16.h>
#include <math.h>
#include <stdint.h>

#define ENT   52
#define INNER 64
#define BB    8
#define SS    512
#define HH    768
#define NOUT  6656    /* ENT*2*INNER */
#define KDIM  1536
#define MDIM  4096    /* BB*SS */
#define BIGF  1000000000000.0f

// ---------------- scratch (device globals; no allocations allowed) ----------
__device__ float          g_cls_emb[BB * HH];                       // 24 KB
__device__ __nv_bfloat16  g_qk[(size_t)BB * ENT * SS * 128];        // 54.5 MB [b][e][s][c]
__device__ __nv_bfloat16  g_hidden[(size_t)MDIM * KDIM];            // 12.6 MB
__device__ __nv_bfloat16  g_wbf[(size_t)NOUT * KDIM];               // 20.4 MB
__device__ float2         g_rope[SS * 32];                          // 128 KB (cos,sin)

// ---------------- PTX helpers ----------------------------------------------
__device__ __forceinline__ uint32_t smem_u32(const void* p) {
    uint32_t a;
    asm("{ .reg .u64 t; cvta.to.shared.u64 t, %1; cvt.u32.u64 %0, t; }" : "=r"(a) : "l"(p));
    return a;
}
__device__ __forceinline__ void cp_async16(uint32_t dst, const void* src) {
    asm volatile("cp.async.cg.shared.global [%0], [%1], 16;\n" :: "r"(dst), "l"(src) : "memory");
}
__device__ __forceinline__ void cp_commit() {
    asm volatile("cp.async.commit_group;\n" ::: "memory");
}
__device__ __forceinline__ void ldsm4(uint32_t* r, uint32_t addr) {
    asm volatile("ldmatrix.sync.aligned.m8n8.x4.shared.b16 {%0,%1,%2,%3}, [%4];"
                 : "=r"(r[0]), "=r"(r[1]), "=r"(r[2]), "=r"(r[3]) : "r"(addr));
}
__device__ __forceinline__ void mma16816(float* c, const uint32_t* a, const uint32_t* b) {
    asm volatile(
        "mma.sync.aligned.m16n8k16.row.col.f32.bf16.bf16.f32 "
        "{%0,%1,%2,%3}, {%4,%5,%6,%7}, {%8,%9}, {%0,%1,%2,%3};"
        : "+f"(c[0]), "+f"(c[1]), "+f"(c[2]), "+f"(c[3])
        : "r"(a[0]), "r"(a[1]), "r"(a[2]), "r"(a[3]), "r"(b[0]), "r"(b[1]));
}

// ---------------------------------------------------------------------------
// Kernel 1 (fused prep): blocks [0,9984) convert weights, [9984,10048) build
// rope table, [10048,10072) run the GRU cells. All independent work — runs
// concurrently instead of 3 serial launches.
// ---------------------------------------------------------------------------
#define CONV_BLOCKS (NOUT * KDIM / 4 / 256)   /* 9984 */
#define ROPE_BLOCKS 64
#define GRU_BLOCKS  24
#define PREP_BLOCKS (CONV_BLOCKS + ROPE_BLOCKS + GRU_BLOCKS)

__global__ __launch_bounds__(256) void prep_kernel(
    const float* __restrict__ dw,
    const float* __restrict__ cls, const float* __restrict__ h0,
    const float* __restrict__ w_ih_f, const float* __restrict__ w_hh_f,
    const float* __restrict__ b_ih_f, const float* __restrict__ b_hh_f,
    const float* __restrict__ w_ih_b, const float* __restrict__ w_hh_b,
    const float* __restrict__ b_ih_b, const float* __restrict__ b_hh_b)
{
    const int bid = blockIdx.x;

    if (bid < CONV_BLOCKS) {
        // ---- weights fp32 -> bf16 ----
        size_t i = ((size_t)bid * 256 + threadIdx.x) * 4;
        float4 v = *(const float4*)(dw + i);
        __nv_bfloat162 p0 = __floats2bfloat162_rn(v.x, v.y);
        __nv_bfloat162 p1 = __floats2bfloat162_rn(v.z, v.w);
        uint2 o; o.x = *(uint32_t*)&p0; o.y = *(uint32_t*)&p1;
        *(uint2*)(g_wbf + i) = o;
        return;
    }
    if (bid < CONV_BLOCKS + ROPE_BLOCKS) {
        // ---- rope table ----
        int idx = (bid - CONV_BLOCKS) * 256 + threadIdx.x;   // 0..16383
        int s = idx >> 5, t = idx & 31;
        float invf = powf(10000.0f, -2.0f * (float)t / 64.0f);
        float sn, cs;
        sincosf((float)s * invf, &sn, &cs);
        g_rope[idx] = make_float2(cs, sn);
        return;
    }

    // ---- GRU: 24 blocks = 12 unit-chunks x 2 dirs; 256 thr = 32 units x 8 b
    const int gid = bid - (CONV_BLOCKS + ROPE_BLOCKS);
    const int dir = gid / 12;
    const int u   = (gid % 12) * 32 + (threadIdx.x >> 3);
    const int b   = threadIdx.x & 7;

    const float* w_ih = dir ? w_ih_b : w_ih_f;
    const float* w_hh = dir ? w_hh_b : w_hh_f;
    const float* b_ih = dir ? b_ih_b : b_ih_f;
    const float* b_hh = dir ? b_hh_b : b_hh_f;

    __shared__ float xs[BB][HH + 4];
    __shared__ float hs[BB][384 + 4];

    for (int i = threadIdx.x; i < BB * HH; i += blockDim.x)
        xs[i / HH][i % HH] = cls[i];
    for (int i = threadIdx.x; i < BB * 384; i += blockDim.x)
        hs[i / 384][i % 384] = h0[(size_t)dir * BB * 384 + i];
    __syncthreads();

    float gi[3], gh[3];
#pragma unroll
    for (int g = 0; g < 3; g++) {
        const float* w = w_ih + (size_t)(g * 384 + u) * HH;
        float acc = b_ih[g * 384 + u];
#pragma unroll 4
        for (int k = 0; k < HH; k += 4) {
            float4 wv = *(const float4*)(w + k);
            acc += wv.x * xs[b][k] + wv.y * xs[b][k + 1] + wv.z * xs[b][k + 2] + wv.w * xs[b][k + 3];
        }
        gi[g] = acc;
        const float* w2 = w_hh + (size_t)(g * 384 + u) * 384;
        float acc2 = b_hh[g * 384 + u];
#pragma unroll 4
        for (int k = 0; k < 384; k += 4) {
            float4 wv = *(const float4*)(w2 + k);
            acc2 += wv.x * hs[b][k] + wv.y * hs[b][k + 1] + wv.z * hs[b][k + 2] + wv.w * hs[b][k + 3];
        }
        gh[g] = acc2;
    }
    float r = 1.0f / (1.0f + expf(-(gi[0] + gh[0])));
    float z = 1.0f / (1.0f + expf(-(gi[1] + gh[1])));
    float n = tanhf(gi[2] + r * gh[2]);
    g_cls_emb[b * HH + dir * 384 + u] = (1.0f - z) * n + z * hs[b][u];
}

// ---------------------------------------------------------------------------
// Kernel 1c: hidden bf16 = concat(lhs, cls_emb broadcast)  (needs GRU done)
// ---------------------------------------------------------------------------
__global__ void build_hidden_kernel(const float* __restrict__ lhs)
{
    size_t gid = (size_t)blockIdx.x * blockDim.x + threadIdx.x;
    int m  = (int)(gid / 384);
    int kq = (int)(gid % 384) * 4;
    float4 v;
    if (kq < HH) v = *(const float4*)(lhs + (size_t)m * HH + kq);
    else         v = *(const float4*)(g_cls_emb + (m >> 9) * HH + (kq - HH));
    __nv_bfloat162 p0 = __floats2bfloat162_rn(v.x, v.y);
    __nv_bfloat162 p1 = __floats2bfloat162_rn(v.z, v.w);
    uint2 o; o.x = *(uint32_t*)&p0; o.y = *(uint32_t*)&p1;
    *(uint2*)(g_hidden + (size_t)m * KDIM + kq) = o;
}

// ---------------------------------------------------------------------------
// Kernel 2: dense GEMM via mma.sync bf16. CTA 256x128x32, 8 warps (4Mx2N),
// warp tile 64x64, 4-stage cp.async. Epilogue: bias + RoPE -> bf16 g_qk.
// grid (52 entities, 16 m-tiles), 256 threads, occ 1.
// ---------------------------------------------------------------------------
#define AROWB 80                       /* 32 bf16 + 8B pad */
#define ASTGB (256 * AROWB)            /* 20480 */
#define BSTGB (128 * AROWB)            /* 10240 */
#define DSMEM_DENSE (4 * (ASTGB + BSTGB))   /* 122880 */

__global__ __launch_bounds__(256, 1) void dense_mma_kernel(const float* __restrict__ db)
{
    extern __shared__ char dsm[];
    const uint32_t sA = smem_u32(dsm);
    const uint32_t sB = sA + 4 * ASTGB;
    __shared__ float bias_s[128];

    const int e  = blockIdx.x;
    const int mt = blockIdx.y;
    const int m0 = mt * 256;
    const int n0 = e * 128;
    const int tid = threadIdx.x;
    const int lane = tid & 31;
    const int wid  = tid >> 5;
    const int warpM = wid >> 1;       // 0..3 (64 rows each)
    const int warpN = wid & 1;        // 0..1 (64 cols each)

    if (tid < 128) bias_s[tid] = db[n0 + tid];

    const __nv_bfloat16* gA = g_hidden + (size_t)m0 * KDIM;
    const __nv_bfloat16* gB = g_wbf    + (size_t)n0 * KDIM;

    auto load_chunk = [&](int st, int ck) {
        const __nv_bfloat16* ga = gA + ck * 32;
        const __nv_bfloat16* gb = gB + ck * 32;
#pragma unroll
        for (int i = 0; i < 4; i++) {              // A: 256 rows x 4 segs
            int id  = i * 256 + tid;               // 0..1023
            int row = id >> 2, seg = id & 3;
            cp_async16(sA + (uint32_t)(st * ASTGB + row * AROWB + seg * 16),
                       ga + (size_t)row * KDIM + seg * 8);
        }
#pragma unroll
        for (int i = 0; i < 2; i++) {              // B: 128 rows x 4 segs
            int id  = i * 256 + tid;               // 0..511
            int row = id >> 2, seg = id & 3;
            cp_async16(sB + (uint32_t)(st * BSTGB + row * AROWB + seg * 16),
                       gb + (size_t)row * KDIM + seg * 8);
        }
        cp_commit();
    };

    float acc[4][8][4];
#pragma unroll
    for (int i = 0; i < 4; i++)
#pragma unroll
        for (int j = 0; j < 8; j++)
#pragma unroll
            for (int r = 0; r < 4; r++) acc[i][j][r] = 0.0f;

#pragma unroll
    for (int s = 0; s < 3; s++) load_chunk(s, s);

    const int NCH = KDIM / 32;   // 48
    for (int k = 0; k < NCH; k++) {
        int st = k & 3;
        asm volatile("cp.async.wait_group 2;\n" ::: "memory");
        __syncthreads();
        if (k + 3 < NCH) load_chunk((k + 3) & 3, k + 3);
        else             cp_commit();

        uint32_t aS = sA + st * ASTGB;
        uint32_t bS = sB + st * BSTGB;
#pragma unroll
        for (int kstep = 0; kstep < 2; kstep++) {
            uint32_t areg[4][4];
#pragma unroll
            for (int mi = 0; mi < 4; mi++)
                ldsm4(areg[mi], aS + (uint32_t)((warpM * 64 + mi * 16 + (lane & 15)) * AROWB
                                                + kstep * 32 + (lane >> 4) * 16));
#pragma unroll
            for (int jp = 0; jp < 4; jp++) {
                uint32_t t4[4];
                ldsm4(t4, bS + (uint32_t)((warpN * 64 + jp * 16 + (lane & 15)) * AROWB
                                          + kstep * 32 + (lane >> 4) * 16));
                uint32_t b0[2] = { t4[0], t4[2] };
                uint32_t b1[2] = { t4[1], t4[3] };
#pragma unroll
                for (int mi = 0; mi < 4; mi++) {
                    mma16816(acc[mi][jp * 2],     areg[mi], b0);
                    mma16816(acc[mi][jp * 2 + 1], areg[mi], b1);
                }
            }
        }
    }

    // ---- epilogue: bias + RoPE, bf16 store ---------------------------------
    const int g = lane >> 2, q = lane & 3;
#pragma unroll
    for (int mi = 0; mi < 4; mi++) {
#pragma unroll
        for (int h = 0; h < 2; h++) {
            int m = m0 + warpM * 64 + mi * 16 + h * 8 + g;
            int s = m & 511;
            int bsel = m >> 9;
            size_t obase = (((size_t)(bsel * ENT + e)) * SS + s) * 128;
#pragma unroll
            for (int j = 0; j < 8; j++) {
                int c = warpN * 64 + j * 8 + 2 * q;
                float x = acc[mi][j][h * 2]     + bias_s[c];
                float y = acc[mi][j][h * 2 + 1] + bias_s[c + 1];
                int t = (c & 63) >> 1;
                float2 rc = g_rope[s * 32 + t];
                float rx = x * rc.x - y * rc.y;
                float ry = y * rc.x + x * rc.y;
                __nv_bfloat162 p = __floats2bfloat162_rn(rx, ry);
                *(uint32_t*)(g_qk + obase + c) = *(uint32_t*)&p;
            }
        }
    }
}

// ---------------------------------------------------------------------------
// Kernel 3: logits via mma.sync bf16 + causal-tile skip + streaming stores.
// grid (16, 52, 8), 256 threads.  (validated round 4, unchanged)
// ---------------------------------------------------------------------------
#define QROWB 144
#define DSMEM_LOG (2 * 128 * QROWB)

__global__ __launch_bounds__(256) void logits_kernel(const float* __restrict__ mask,
                                                     float* __restrict__ out)
{
    extern __shared__ char lsm[];
    const uint32_t sQ = smem_u32(lsm);
    const uint32_t sK = sQ + 128 * QROWB;

    const int e = blockIdx.y;
    const int b = blockIdx.z;
    const int mt = blockIdx.x >> 2, nt = blockIdx.x & 3;
    const int m0 = mt * 128, n0 = nt * 128;
    const int tid = threadIdx.x;

    const size_t rowbase = ((size_t)(b * ENT + e)) * SS;

    if (mt > nt) {
        int cg = (tid & 31) * 4;
        float4 v;
        {
            float p0 = mask[b * SS + n0 + cg];
            float p1 = mask[b * SS + n0 + cg + 1];
            float p2 = mask[b * SS + n0 + cg + 2];
            float p3 = mask[b * SS + n0 + cg + 3];
            v = make_float4(((p0 - 1.0f) * BIGF - BIGF) * 0.125f,
                            ((p1 - 1.0f) * BIGF - BIGF) * 0.125f,
                            ((p2 - 1.0f) * BIGF - BIGF) * 0.125f,
                            ((p3 - 1.0f) * BIGF - BIGF) * 0.125f);
        }
        for (int r = tid >> 5; r < 128; r += 8)
            __stcs((float4*)(out + (rowbase + m0 + r) * SS + n0 + cg), v);
        return;
    }

    const int lane = tid & 31;
    const int wid  = tid >> 5;
    const int warpM = wid >> 2;
    const int warpN = wid & 3;

#pragma unroll
    for (int i = 0; i < 4; i++) {
        int id  = tid * 4 + i;
        int row = id >> 3, seg = id & 7;
        uint32_t off = (uint32_t)(row * QROWB + seg * 16);
        cp_async16(sQ + off, g_qk + (rowbase + m0 + row) * 128 + seg * 8);
        cp_async16(sK + off, g_qk + (rowbase + n0 + row) * 128 + 64 + seg * 8);
    }
    cp_commit();
    asm volatile("cp.async.wait_group 0;\n" ::: "memory");
    __syncthreads();

    float acc[4][4][4];
#pragma unroll
    for (int i = 0; i < 4; i++)
#pragma unroll
        for (int j = 0; j < 4; j++)
#pragma unroll
            for (int r = 0; r < 4; r++) acc[i][j][r] = 0.0f;

#pragma unroll
    for (int kstep = 0; kstep < 4; kstep++) {
        uint32_t areg[4][4], breg[4][2];
#pragma unroll
        for (int mi = 0; mi < 4; mi++)
            ldsm4(areg[mi], sQ + (uint32_t)((warpM * 64 + mi * 16 + (lane & 15)) * QROWB
                                            + kstep * 32 + (lane >> 4) * 16));
#pragma unroll
        for (int jp = 0; jp < 2; jp++) {
            uint32_t t4[4];
            ldsm4(t4, sK + (uint32_t)((warpN * 32 + jp * 16 + (lane & 15)) * QROWB
                                      + kstep * 32 + (lane >> 4) * 16));
            breg[jp * 2][0]     = t4[0];
            breg[jp * 2 + 1][0] = t4[1];
            breg[jp * 2][1]     = t4[2];
            breg[jp * 2 + 1][1] = t4[3];
        }
#pragma unroll
        for (int mi = 0; mi < 4; mi++)
#pragma unroll
            for (int j = 0; j < 4; j++)
                mma16816(acc[mi][j], areg[mi], breg[j]);
    }

    const int g = lane >> 2, q = lane & 3;
    const int nbase = n0 + warpN * 32;
    float p0[4], p1[4];
#pragma unroll
    for (int j = 0; j < 4; j++) {
        int c = nbase + j * 8 + 2 * q;
        p0[j] = mask[b * SS + c];
        p1[j] = mask[b * SS + c + 1];
    }

#pragma unroll
    for (int mi = 0; mi < 4; mi++) {
#pragma unroll
        for (int h = 0; h < 2; h++) {
            int m = m0 + warpM * 64 + mi * 16 + h * 8 + g;
            size_t orow = (rowbase + m) * SS;
#pragma unroll
            for (int j = 0; j < 4; j++) {
                int c = nbase + j * 8 + 2 * q;
                float x = acc[mi][j][h * 2];
                float y = acc[mi][j][h * 2 + 1];
                x = x * p0[j] - (1.0f - p0[j]) * BIGF;
                y = y * p1[j] - (1.0f - p1[j]) * BIGF;
                if (m > c)     x -= BIGF;
                if (m > c + 1) y -= BIGF;
                __stcs((float2*)(out + orow + c), make_float2(x * 0.125f, y * 0.125f));
            }
        }
    }
}

// ---------------------------------------------------------------------------
extern "C" void kernel_launch(void* const* d_in, const int* in_sizes, int n_in,
                              void* d_out, int out_size)
{
    const float* lhs    = (const float*)d_in[0];
    const float* cls    = (const float*)d_in[1];
    const float* h0     = (const float*)d_in[2];
    const float* mask   = (const float*)d_in[3];
    const float* w_ih_f = (const float*)d_in[4];
    const float* w_hh_f = (const float*)d_in[5];
    const float* b_ih_f = (const float*)d_in[6];
    const float* b_hh_f = (const float*)d_in[7];
    const float* w_ih_b = (const float*)d_in[8];
    const float* w_hh_b = (const float*)d_in[9];
    const float* b_ih_b = (const float*)d_in[10];
    const float* b_hh_b = (const float*)d_in[11];
    const float* dw     = (const float*)d_in[12];
    const float* db     = (const float*)d_in[13];
    float* out = (float*)d_out;

    cudaFuncSetAttribute(dense_mma_kernel, cudaFuncAttributeMaxDynamicSharedMemorySize, DSMEM_DENSE);
    cudaFuncSetAttribute(logits_kernel,    cudaFuncAttributeMaxDynamicSharedMemorySize, DSMEM_LOG);

    prep_kernel<<<PREP_BLOCKS, 256>>>(dw, cls, h0, w_ih_f, w_hh_f, b_ih_f, b_hh_f,
                                      w_ih_b, w_hh_b, b_ih_b, b_hh_b);
    build_hidden_kernel<<<(MDIM * KDIM / 4) / 256, 256>>>(lhs);

    dense_mma_kernel<<<dim3(ENT, MDIM / 256), 256, DSMEM_DENSE>>>(db);

    logits_kernel<<<dim3(16, ENT, BB), 256, DSMEM_LOG>>>(mask, out);
}

// round 6
// speedup vs baseline: 1.2729x; 1.2729x over previous
#include <cuda_runtime.h>
#include <cuda_bf16.h>
#include <math.h>
#include <stdint.h>

#define ENT   52
#define INNER 64
#define BB    8
#define SS    512
#define HH    768
#define NOUT  6656    /* ENT*2*INNER */
#define KDIM  1536
#define MDIM  4096    /* BB*SS */
#define BIGF  1000000000000.0f

// ---------------- scratch (device globals; no allocations allowed) ----------
__device__ float          g_cls_emb[BB * HH];                       // 24 KB
__device__ float          g_clsw[BB * NOUT];                        // 213 KB ext. bias
__device__ __nv_bfloat16  g_qk[(size_t)BB * ENT * SS * 128];        // 54.5 MB [b][e][s][c]
__device__ __nv_bfloat16  g_hidden[(size_t)MDIM * HH];              // 6.3 MB (lhs bf16)
__device__ __nv_bfloat16  g_wbf[(size_t)NOUT * HH];                 // 10.2 MB (W1 bf16)
__device__ float2         g_rope[SS * 32];                          // 128 KB (cos,sin)

// ---------------- PTX helpers ----------------------------------------------
__device__ __forceinline__ uint32_t smem_u32(const void* p) {
    uint32_t a;
    asm("{ .reg .u64 t; cvta.to.shared.u64 t, %1; cvt.u32.u64 %0, t; }" : "=r"(a) : "l"(p));
    return a;
}
__device__ __forceinline__ void cp_async16(uint32_t dst, const void* src) {
    asm volatile("cp.async.cg.shared.global [%0], [%1], 16;\n" :: "r"(dst), "l"(src) : "memory");
}
__device__ __forceinline__ void cp_commit() {
    asm volatile("cp.async.commit_group;\n" ::: "memory");
}
__device__ __forceinline__ void ldsm4(uint32_t* r, uint32_t addr) {
    asm volatile("ldmatrix.sync.aligned.m8n8.x4.shared.b16 {%0,%1,%2,%3}, [%4];"
                 : "=r"(r[0]), "=r"(r[1]), "=r"(r[2]), "=r"(r[3]) : "r"(addr));
}
__device__ __forceinline__ void mma16816(float* c, const uint32_t* a, const uint32_t* b) {
    asm volatile(
        "mma.sync.aligned.m16n8k16.row.col.f32.bf16.bf16.f32 "
        "{%0,%1,%2,%3}, {%4,%5,%6,%7}, {%8,%9}, {%0,%1,%2,%3};"
        : "+f"(c[0]), "+f"(c[1]), "+f"(c[2]), "+f"(c[3])
        : "r"(a[0]), "r"(a[1]), "r"(a[2]), "r"(a[3]), "r"(b[0]), "r"(b[1]));
}

// ---------------------------------------------------------------------------
// Kernel 1 (fused prep): all mutually independent work in one launch:
//   [0, 4992)            : W1 (first 768 cols of dense_w) fp32 -> bf16
//   [4992, 8064)         : lhs fp32 -> bf16 (g_hidden)
//   [8064, 8128)         : rope table
//   [8128, 8152)         : GRU cells
// ---------------------------------------------------------------------------
#define CONVB (NOUT * HH / 4 / 256)    /* 4992 */
#define BHB   (MDIM * HH / 4 / 256)    /* 3072 */
#define ROPEB 64
#define GRUB  24
#define PREPB (CONVB + BHB + ROPEB + GRUB)

__global__ __launch_bounds__(256) void prep_kernel(
    const float* __restrict__ dw, const float* __restrict__ lhs,
    const float* __restrict__ cls, const float* __restrict__ h0,
    const float* __restrict__ w_ih_f, const float* __restrict__ w_hh_f,
    const float* __restrict__ b_ih_f, const float* __restrict__ b_hh_f,
    const float* __restrict__ w_ih_b, const float* __restrict__ w_hh_b,
    const float* __restrict__ b_ih_b, const float* __restrict__ b_hh_b)
{
    const int bid = blockIdx.x;

    if (bid < CONVB) {
        // ---- W1 fp32 -> bf16 (row stride KDIM in source, HH in dest) ----
        int i = bid * 256 + threadIdx.x;
        int n  = i / 192;
        int kq = (i % 192) * 4;
        float4 v = *(const float4*)(dw + (size_t)n * KDIM + kq);
        __nv_bfloat162 p0 = __floats2bfloat162_rn(v.x, v.y);
        __nv_bfloat162 p1 = __floats2bfloat162_rn(v.z, v.w);
        uint2 o; o.x = *(uint32_t*)&p0; o.y = *(uint32_t*)&p1;
        *(uint2*)(g_wbf + (size_t)n * HH + kq) = o;
        return;
    }
    if (bid < CONVB + BHB) {
        // ---- lhs fp32 -> bf16 ----
        size_t gid = (size_t)(bid - CONVB) * 256 + threadIdx.x;
        size_t i = gid * 4;
        float4 v = *(const float4*)(lhs + i);
        __nv_bfloat162 p0 = __floats2bfloat162_rn(v.x, v.y);
        __nv_bfloat162 p1 = __floats2bfloat162_rn(v.z, v.w);
        uint2 o; o.x = *(uint32_t*)&p0; o.y = *(uint32_t*)&p1;
        *(uint2*)(g_hidden + i) = o;
        return;
    }
    if (bid < CONVB + BHB + ROPEB) {
        // ---- rope table ----
        int idx = (bid - CONVB - BHB) * 256 + threadIdx.x;
        int s = idx >> 5, t = idx & 31;
        float invf = powf(10000.0f, -2.0f * (float)t / 64.0f);
        float sn, cs;
        sincosf((float)s * invf, &sn, &cs);
        g_rope[idx] = make_float2(cs, sn);
        return;
    }

    // ---- GRU: 24 blocks = 12 unit-chunks x 2 dirs; 256 thr = 32 units x 8 b
    const int gid = bid - (CONVB + BHB + ROPEB);
    const int dir = gid / 12;
    const int u   = (gid % 12) * 32 + (threadIdx.x >> 3);
    const int b   = threadIdx.x & 7;

    const float* w_ih = dir ? w_ih_b : w_ih_f;
    const float* w_hh = dir ? w_hh_b : w_hh_f;
    const float* b_ih = dir ? b_ih_b : b_ih_f;
    const float* b_hh = dir ? b_hh_b : b_hh_f;

    __shared__ float xs[BB][HH + 4];
    __shared__ float hs[BB][384 + 4];

    for (int i = threadIdx.x; i < BB * HH; i += blockDim.x)
        xs[i / HH][i % HH] = cls[i];
    for (int i = threadIdx.x; i < BB * 384; i += blockDim.x)
        hs[i / 384][i % 384] = h0[(size_t)dir * BB * 384 + i];
    __syncthreads();

    float gi[3], gh[3];
#pragma unroll
    for (int g = 0; g < 3; g++) {
        const float* w = w_ih + (size_t)(g * 384 + u) * HH;
        float acc = b_ih[g * 384 + u];
#pragma unroll 4
        for (int k = 0; k < HH; k += 4) {
            float4 wv = *(const float4*)(w + k);
            acc += wv.x * xs[b][k] + wv.y * xs[b][k + 1] + wv.z * xs[b][k + 2] + wv.w * xs[b][k + 3];
        }
        gi[g] = acc;
        const float* w2 = w_hh + (size_t)(g * 384 + u) * 384;
        float acc2 = b_hh[g * 384 + u];
#pragma unroll 4
        for (int k = 0; k < 384; k += 4) {
            float4 wv = *(const float4*)(w2 + k);
            acc2 += wv.x * hs[b][k] + wv.y * hs[b][k + 1] + wv.z * hs[b][k + 2] + wv.w * hs[b][k + 3];
        }
        gh[g] = acc2;
    }
    float r = 1.0f / (1.0f + expf(-(gi[0] + gh[0])));
    float z = 1.0f / (1.0f + expf(-(gi[1] + gh[1])));
    float n = tanhf(gi[2] + r * gh[2]);
    g_cls_emb[b * HH + dir * 384 + u] = (1.0f - z) * n + z * hs[b][u];
}

// ---------------------------------------------------------------------------
// Kernel 1b: extended bias  clsw[b][n] = db[n] + cls_emb[b,:] . W2[n,:]
// grid 26, 256 threads (one n per thread, 8 batches in registers).
// ---------------------------------------------------------------------------
__global__ __launch_bounds__(256) void clsw_kernel(const float* __restrict__ dw,
                                                   const float* __restrict__ db)
{
    __shared__ float cl[BB][HH + 4];
    for (int i = threadIdx.x; i < BB * HH; i += 256)
        cl[i / HH][i % HH] = g_cls_emb[i];
    __syncthreads();

    const int n = blockIdx.x * 256 + threadIdx.x;
    const float* w = dw + (size_t)n * KDIM + HH;
    float acc[BB];
#pragma unroll
    for (int b = 0; b < BB; b++) acc[b] = 0.0f;
#pragma unroll 4
    for (int k = 0; k < HH; k += 4) {
        float4 wv = *(const float4*)(w + k);
#pragma unroll
        for (int b = 0; b < BB; b++)
            acc[b] += wv.x * cl[b][k] + wv.y * cl[b][k + 1]
                    + wv.z * cl[b][k + 2] + wv.w * cl[b][k + 3];
    }
    float bias = db[n];
#pragma unroll
    for (int b = 0; b < BB; b++) g_clsw[b * NOUT + n] = acc[b] + bias;
}

// ---------------------------------------------------------------------------
// Kernel 2: dense GEMM via mma.sync bf16, K=768. CTA 128x128x32, 8 warps,
// warp 64x32, 4-stage cp.async, occ 2 (validated R3/R4 shape).
// Epilogue: ext-bias + RoPE -> bf16 g_qk. grid (52, 32), 256 threads.
// ---------------------------------------------------------------------------
#define AROWB 80
#define STGB  (128 * AROWB)
#define DSMEM_DENSE (8 * STGB)

__global__ __launch_bounds__(256, 2) void dense_mma_kernel()
{
    extern __shared__ char dsm[];
    const uint32_t sA = smem_u32(dsm);
    const uint32_t sB = sA + 4 * STGB;
    __shared__ float bias_s[128];

    const int e  = blockIdx.x;
    const int mt = blockIdx.y;
    const int m0 = mt * 128;
    const int n0 = e * 128;
    const int bidx = mt >> 2;          // batch of this m-tile
    const int tid = threadIdx.x;
    const int lane = tid & 31;
    const int wid  = tid >> 5;
    const int warpM = wid >> 2;
    const int warpN = wid & 3;

    if (tid < 128) bias_s[tid] = g_clsw[bidx * NOUT + n0 + tid];

    const __nv_bfloat16* gA = g_hidden + (size_t)m0 * HH;
    const __nv_bfloat16* gB = g_wbf    + (size_t)n0 * HH;

    auto load_chunk = [&](int st, int ck) {
        const __nv_bfloat16* ga = gA + ck * 32;
        const __nv_bfloat16* gb = gB + ck * 32;
#pragma unroll
        for (int i = 0; i < 2; i++) {
            int id  = tid * 2 + i;
            int row = id >> 2, seg = id & 3;
            uint32_t off = (uint32_t)(st * STGB + row * AROWB + seg * 16);
            cp_async16(sA + off, ga + (size_t)row * HH + seg * 8);
            cp_async16(sB + off, gb + (size_t)row * HH + seg * 8);
        }
        cp_commit();
    };

    float acc[4][4][4];
#pragma unroll
    for (int i = 0; i < 4; i++)
#pragma unroll
        for (int j = 0; j < 4; j++)
#pragma unroll
            for (int r = 0; r < 4; r++) acc[i][j][r] = 0.0f;

#pragma unroll
    for (int s = 0; s < 3; s++) load_chunk(s, s);

    const int NCH = HH / 32;   // 24
    for (int k = 0; k < NCH; k++) {
        int st = k & 3;
        asm volatile("cp.async.wait_group 2;\n" ::: "memory");
        __syncthreads();
        if (k + 3 < NCH) load_chunk((k + 3) & 3, k + 3);
        else             cp_commit();

        uint32_t aS = sA + st * STGB;
        uint32_t bS = sB + st * STGB;
#pragma unroll
        for (int kstep = 0; kstep < 2; kstep++) {
            uint32_t areg[4][4], breg[4][2];
#pragma unroll
            for (int mi = 0; mi < 4; mi++)
                ldsm4(areg[mi], aS + (uint32_t)((warpM * 64 + mi * 16 + (lane & 15)) * AROWB
                                                + kstep * 32 + (lane >> 4) * 16));
#pragma unroll
            for (int jp = 0; jp < 2; jp++) {
                uint32_t t4[4];
                ldsm4(t4, bS + (uint32_t)((warpN * 32 + jp * 16 + (lane & 15)) * AROWB
                                          + kstep * 32 + (lane >> 4) * 16));
                breg[jp * 2][0]     = t4[0];
                breg[jp * 2 + 1][0] = t4[1];
                breg[jp * 2][1]     = t4[2];
                breg[jp * 2 + 1][1] = t4[3];
            }
#pragma unroll
            for (int mi = 0; mi < 4; mi++)
#pragma unroll
                for (int j = 0; j < 4; j++)
                    mma16816(acc[mi][j], areg[mi], breg[j]);
        }
    }

    // ---- epilogue: ext-bias + RoPE, bf16 store -----------------------------
    const int g = lane >> 2, q = lane & 3;
#pragma unroll
    for (int mi = 0; mi < 4; mi++) {
#pragma unroll
        for (int h = 0; h < 2; h++) {
            int m = m0 + warpM * 64 + mi * 16 + h * 8 + g;
            int s = m & 511;
            size_t obase = (((size_t)(bidx * ENT + e)) * SS + s) * 128;
#pragma unroll
            for (int j = 0; j < 4; j++) {
                int c = warpN * 32 + j * 8 + 2 * q;
                float x = acc[mi][j][h * 2]     + bias_s[c];
                float y = acc[mi][j][h * 2 + 1] + bias_s[c + 1];
                int t = (c & 63) >> 1;
                float2 rc = g_rope[s * 32 + t];
                float rx = x * rc.x - y * rc.y;
                float ry = y * rc.x + x * rc.y;
                __nv_bfloat162 p = __floats2bfloat162_rn(rx, ry);
                *(uint32_t*)(g_qk + obase + c) = *(uint32_t*)&p;
            }
        }
    }
}

// ---------------------------------------------------------------------------
// Kernel 3: logits via mma.sync bf16 + causal-tile skip + streaming stores.
// (validated R4/R5: 102 us, near memory floor — unchanged)
// ---------------------------------------------------------------------------
#define QROWB 144
#define DSMEM_LOG (2 * 128 * QROWB)

__global__ __launch_bounds__(256) void logits_kernel(const float* __restrict__ mask,
                                                     float* __restrict__ out)
{
    extern __shared__ char lsm[];
    const uint32_t sQ = smem_u32(lsm);
    const uint32_t sK = sQ + 128 * QROWB;

    const int e = blockIdx.y;
    const int b = blockIdx.z;
    const int mt = blockIdx.x >> 2, nt = blockIdx.x & 3;
    const int m0 = mt * 128, n0 = nt * 128;
    const int tid = threadIdx.x;

    const size_t rowbase = ((size_t)(b * ENT + e)) * SS;

    if (mt > nt) {
        int cg = (tid & 31) * 4;
        float4 v;
        {
            float p0 = mask[b * SS + n0 + cg];
            float p1 = mask[b * SS + n0 + cg + 1];
            float p2 = mask[b * SS + n0 + cg + 2];
            float p3 = mask[b * SS + n0 + cg + 3];
            v = make_float4(((p0 - 1.0f) * BIGF - BIGF) * 0.125f,
                            ((p1 - 1.0f) * BIGF - BIGF) * 0.125f,
                            ((p2 - 1.0f) * BIGF - BIGF) * 0.125f,
                            ((p3 - 1.0f) * BIGF - BIGF) * 0.125f);
        }
        for (int r = tid >> 5; r < 128; r += 8)
            __stcs((float4*)(out + (rowbase + m0 + r) * SS + n0 + cg), v);
        return;
    }

    const int lane = tid & 31;
    const int wid  = tid >> 5;
    const int warpM = wid >> 2;
    const int warpN = wid & 3;

#pragma unroll
    for (int i = 0; i < 4; i++) {
        int id  = tid * 4 + i;
        int row = id >> 3, seg = id & 7;
        uint32_t off = (uint32_t)(row * QROWB + seg * 16);
        cp_async16(sQ + off, g_qk + (rowbase + m0 + row) * 128 + seg * 8);
        cp_async16(sK + off, g_qk + (rowbase + n0 + row) * 128 + 64 + seg * 8);
    }
    cp_commit();
    asm volatile("cp.async.wait_group 0;\n" ::: "memory");
    __syncthreads();

    float acc[4][4][4];
#pragma unroll
    for (int i = 0; i < 4; i++)
#pragma unroll
        for (int j = 0; j < 4; j++)
#pragma unroll
            for (int r = 0; r < 4; r++) acc[i][j][r] = 0.0f;

#pragma unroll
    for (int kstep = 0; kstep < 4; kstep++) {
        uint32_t areg[4][4], breg[4][2];
#pragma unroll
        for (int mi = 0; mi < 4; mi++)
            ldsm4(areg[mi], sQ + (uint32_t)((warpM * 64 + mi * 16 + (lane & 15)) * QROWB
                                            + kstep * 32 + (lane >> 4) * 16));
#pragma unroll
        for (int jp = 0; jp < 2; jp++) {
            uint32_t t4[4];
            ldsm4(t4, sK + (uint32_t)((warpN * 32 + jp * 16 + (lane & 15)) * QROWB
                                      + kstep * 32 + (lane >> 4) * 16));
            breg[jp * 2][0]     = t4[0];
            breg[jp * 2 + 1][0] = t4[1];
            breg[jp * 2][1]     = t4[2];
            breg[jp * 2 + 1][1] = t4[3];
        }
#pragma unroll
        for (int mi = 0; mi < 4; mi++)
#pragma unroll
            for (int j = 0; j < 4; j++)
                mma16816(acc[mi][j], areg[mi], breg[j]);
    }

    const int g = lane >> 2, q = lane & 3;
    const int nbase = n0 + warpN * 32;
    float p0[4], p1[4];
#pragma unroll
    for (int j = 0; j < 4; j++) {
        int c = nbase + j * 8 + 2 * q;
        p0[j] = mask[b * SS + c];
        p1[j] = mask[b * SS + c + 1];
    }

#pragma unroll
    for (int mi = 0; mi < 4; mi++) {
#pragma unroll
        for (int h = 0; h < 2; h++) {
            int m = m0 + warpM * 64 + mi * 16 + h * 8 + g;
            size_t orow = (rowbase + m) * SS;
#pragma unroll
            for (int j = 0; j < 4; j++) {
                int c = nbase + j * 8 + 2 * q;
                float x = acc[mi][j][h * 2];
                float y = acc[mi][j][h * 2 + 1];
                x = x * p0[j] - (1.0f - p0[j]) * BIGF;
                y = y * p1[j] - (1.0f - p1[j]) * BIGF;
                if (m > c)     x -= BIGF;
                if (m > c + 1) y -= BIGF;
                __stcs((float2*)(out + orow + c), make_float2(x * 0.125f, y * 0.125f));
            }
        }
    }
}

// ---------------------------------------------------------------------------
extern "C" void kernel_launch(void* const* d_in, const int* in_sizes, int n_in,
                              void* d_out, int out_size)
{
    const float* lhs    = (const float*)d_in[0];
    const float* cls    = (const float*)d_in[1];
    const float* h0     = (const float*)d_in[2];
    const float* mask   = (const float*)d_in[3];
    const float* w_ih_f = (const float*)d_in[4];
    const float* w_hh_f = (const float*)d_in[5];
    const float* b_ih_f = (const float*)d_in[6];
    const float* b_hh_f = (const float*)d_in[7];
    const float* w_ih_b = (const float*)d_in[8];
    const float* w_hh_b = (const float*)d_in[9];
    const float* b_ih_b = (const float*)d_in[10];
    const float* b_hh_b = (const float*)d_in[11];
    const float* dw     = (const float*)d_in[12];
    const float* db     = (const float*)d_in[13];
    float* out = (float*)d_out;

    cudaFuncSetAttribute(dense_mma_kernel, cudaFuncAttributeMaxDynamicSharedMemorySize, DSMEM_DENSE);
    cudaFuncSetAttribute(logits_kernel,    cudaFuncAttributeMaxDynamicSharedMemorySize, DSMEM_LOG);

    prep_kernel<<<PREPB, 256>>>(dw, lhs, cls, h0, w_ih_f, w_hh_f, b_ih_f, b_hh_f,
                                w_ih_b, w_hh_b, b_ih_b, b_hh_b);
    clsw_kernel<<<NOUT / 256, 256>>>(dw, db);

    dense_mma_kernel<<<dim3(ENT, MDIM / 128), 256, DSMEM_DENSE>>>();

    logits_kernel<<<dim3(16, ENT, BB), 256, DSMEM_LOG>>>(mask, out);
}

// round 7
// speedup vs baseline: 1.4455x; 1.1357x over previous
#include <cuda_runtime.h>
#include <cuda_bf16.h>
#include <math.h>
#include <stdint.h>

#define ENT   52
#define INNER 64
#define BB    8
#define SS    512
#define HH    768
#define NOUT  6656    /* ENT*2*INNER */
#define KDIM  1536
#define MDIM  4096    /* BB*SS */
#define BIGF  1000000000000.0f

// ---------------- scratch (device globals; no allocations allowed) ----------
__device__ float          g_cls_emb[BB * HH];                       // 24 KB
__device__ float          g_clsw[BB * NOUT];                        // 213 KB ext. bias
__device__ __nv_bfloat16  g_qk[(size_t)BB * ENT * SS * 128];        // 54.5 MB [b][e][s][c]
__device__ __nv_bfloat16  g_hidden[(size_t)MDIM * HH];              // 6.3 MB (lhs bf16)
__device__ __nv_bfloat16  g_wbf[(size_t)NOUT * HH];                 // 10.2 MB (W1 bf16)
__device__ float2         g_rope[SS * 32];                          // 128 KB (cos,sin)

// ---------------- PTX helpers ----------------------------------------------
__device__ __forceinline__ uint32_t smem_u32(const void* p) {
    uint32_t a;
    asm("{ .reg .u64 t; cvta.to.shared.u64 t, %1; cvt.u32.u64 %0, t; }" : "=r"(a) : "l"(p));
    return a;
}
__device__ __forceinline__ void cp_async16(uint32_t dst, const void* src) {
    asm volatile("cp.async.cg.shared.global [%0], [%1], 16;\n" :: "r"(dst), "l"(src) : "memory");
}
__device__ __forceinline__ void cp_commit() {
    asm volatile("cp.async.commit_group;\n" ::: "memory");
}
__device__ __forceinline__ void ldsm4(uint32_t* r, uint32_t addr) {
    asm volatile("ldmatrix.sync.aligned.m8n8.x4.shared.b16 {%0,%1,%2,%3}, [%4];"
                 : "=r"(r[0]), "=r"(r[1]), "=r"(r[2]), "=r"(r[3]) : "r"(addr));
}
__device__ __forceinline__ void mma16816(float* c, const uint32_t* a, const uint32_t* b) {
    asm volatile(
        "mma.sync.aligned.m16n8k16.row.col.f32.bf16.bf16.f32 "
        "{%0,%1,%2,%3}, {%4,%5,%6,%7}, {%8,%9}, {%0,%1,%2,%3};"
        : "+f"(c[0]), "+f"(c[1]), "+f"(c[2]), "+f"(c[3])
        : "r"(a[0]), "r"(a[1]), "r"(a[2]), "r"(a[3]), "r"(b[0]), "r"(b[1]));
}

// ---------------------------------------------------------------------------
// Kernel 1 (fused prep): all mutually independent work in one launch.
// ---------------------------------------------------------------------------
#define CONVB (NOUT * HH / 4 / 256)    /* 4992 */
#define BHB   (MDIM * HH / 4 / 256)    /* 3072 */
#define ROPEB 64
#define GRUB  24
#define PREPB (CONVB + BHB + ROPEB + GRUB)

__global__ __launch_bounds__(256) void prep_kernel(
    const float* __restrict__ dw, const float* __restrict__ lhs,
    const float* __restrict__ cls, const float* __restrict__ h0,
    const float* __restrict__ w_ih_f, const float* __restrict__ w_hh_f,
    const float* __restrict__ b_ih_f, const float* __restrict__ b_hh_f,
    const float* __restrict__ w_ih_b, const float* __restrict__ w_hh_b,
    const float* __restrict__ b_ih_b, const float* __restrict__ b_hh_b)
{
    const int bid = blockIdx.x;

    if (bid < CONVB) {
        int i = bid * 256 + threadIdx.x;
        int n  = i / 192;
        int kq = (i % 192) * 4;
        float4 v = *(const float4*)(dw + (size_t)n * KDIM + kq);
        __nv_bfloat162 p0 = __floats2bfloat162_rn(v.x, v.y);
        __nv_bfloat162 p1 = __floats2bfloat162_rn(v.z, v.w);
        uint2 o; o.x = *(uint32_t*)&p0; o.y = *(uint32_t*)&p1;
        *(uint2*)(g_wbf + (size_t)n * HH + kq) = o;
        return;
    }
    if (bid < CONVB + BHB) {
        size_t gid = (size_t)(bid - CONVB) * 256 + threadIdx.x;
        size_t i = gid * 4;
        float4 v = *(const float4*)(lhs + i);
        __nv_bfloat162 p0 = __floats2bfloat162_rn(v.x, v.y);
        __nv_bfloat162 p1 = __floats2bfloat162_rn(v.z, v.w);
        uint2 o; o.x = *(uint32_t*)&p0; o.y = *(uint32_t*)&p1;
        *(uint2*)(g_hidden + i) = o;
        return;
    }
    if (bid < CONVB + BHB + ROPEB) {
        int idx = (bid - CONVB - BHB) * 256 + threadIdx.x;
        int s = idx >> 5, t = idx & 31;
        float invf = powf(10000.0f, -2.0f * (float)t / 64.0f);
        float sn, cs;
        sincosf((float)s * invf, &sn, &cs);
        g_rope[idx] = make_float2(cs, sn);
        return;
    }

    // ---- GRU ----
    const int gid = bid - (CONVB + BHB + ROPEB);
    const int dir = gid / 12;
    const int u   = (gid % 12) * 32 + (threadIdx.x >> 3);
    const int b   = threadIdx.x & 7;

    const float* w_ih = dir ? w_ih_b : w_ih_f;
    const float* w_hh = dir ? w_hh_b : w_hh_f;
    const float* b_ih = dir ? b_ih_b : b_ih_f;
    const float* b_hh = dir ? b_hh_b : b_hh_f;

    __shared__ float xs[BB][HH + 4];
    __shared__ float hs[BB][384 + 4];

    for (int i = threadIdx.x; i < BB * HH; i += blockDim.x)
        xs[i / HH][i % HH] = cls[i];
    for (int i = threadIdx.x; i < BB * 384; i += blockDim.x)
        hs[i / 384][i % 384] = h0[(size_t)dir * BB * 384 + i];
    __syncthreads();

    float gi[3], gh[3];
#pragma unroll
    for (int g = 0; g < 3; g++) {
        const float* w = w_ih + (size_t)(g * 384 + u) * HH;
        float acc = b_ih[g * 384 + u];
#pragma unroll 4
        for (int k = 0; k < HH; k += 4) {
            float4 wv = *(const float4*)(w + k);
            acc += wv.x * xs[b][k] + wv.y * xs[b][k + 1] + wv.z * xs[b][k + 2] + wv.w * xs[b][k + 3];
        }
        gi[g] = acc;
        const float* w2 = w_hh + (size_t)(g * 384 + u) * 384;
        float acc2 = b_hh[g * 384 + u];
#pragma unroll 4
        for (int k = 0; k < 384; k += 4) {
            float4 wv = *(const float4*)(w2 + k);
            acc2 += wv.x * hs[b][k] + wv.y * hs[b][k + 1] + wv.z * hs[b][k + 2] + wv.w * hs[b][k + 3];
        }
        gh[g] = acc2;
    }
    float r = 1.0f / (1.0f + expf(-(gi[0] + gh[0])));
    float z = 1.0f / (1.0f + expf(-(gi[1] + gh[1])));
    float n = tanhf(gi[2] + r * gh[2]);
    g_cls_emb[b * HH + dir * 384 + u] = (1.0f - z) * n + z * hs[b][u];
}

// ---------------------------------------------------------------------------
// Kernel 1b: extended bias  clsw[b][n] = db[n] + cls_emb[b,:] . W2[n,:]
// ---------------------------------------------------------------------------
__global__ __launch_bounds__(256) void clsw_kernel(const float* __restrict__ dw,
                                                   const float* __restrict__ db)
{
    __shared__ float cl[BB][HH + 4];
    for (int i = threadIdx.x; i < BB * HH; i += 256)
        cl[i / HH][i % HH] = g_cls_emb[i];
    __syncthreads();

    const int n = blockIdx.x * 256 + threadIdx.x;
    const float* w = dw + (size_t)n * KDIM + HH;
    float acc[BB];
#pragma unroll
    for (int b = 0; b < BB; b++) acc[b] = 0.0f;
#pragma unroll 4
    for (int k = 0; k < HH; k += 4) {
        float4 wv = *(const float4*)(w + k);
#pragma unroll
        for (int b = 0; b < BB; b++)
            acc[b] += wv.x * cl[b][k] + wv.y * cl[b][k + 1]
                    + wv.z * cl[b][k + 2] + wv.w * cl[b][k + 3];
    }
    float bias = db[n];
#pragma unroll
    for (int b = 0; b < BB; b++) g_clsw[b * NOUT + n] = acc[b] + bias;
}

// ---------------------------------------------------------------------------
// Kernel 2: dense GEMM via mma.sync bf16, K=768. CTA 128x128x64, 8 warps
// (2Mx4N, warp 64x32), 3-stage cp.async, XOR-swizzled conflict-free smem.
// Epilogue: ext-bias + RoPE -> bf16 g_qk. grid (52, 32), 256 threads, occ 2.
// ---------------------------------------------------------------------------
#define CHKK  64                        /* K per chunk (bf16) -> 128B rows   */
#define STG16 (128 * 128)               /* 16384 B per operand per stage     */
#define NST   3
#define DSMEM_DENSE (2 * NST * STG16)   /* 98304 */

__device__ __forceinline__ uint32_t dswz(int row, int colb) {
    return (uint32_t)(row * 128 + (colb ^ ((row & 7) << 4)));
}

__global__ __launch_bounds__(256, 2) void dense_mma_kernel()
{
    extern __shared__ char dsm[];
    const uint32_t sA = smem_u32(dsm);
    const uint32_t sB = sA + NST * STG16;
    __shared__ float bias_s[128];

    const int e  = blockIdx.x;
    const int mt = blockIdx.y;
    const int m0 = mt * 128;
    const int n0 = e * 128;
    const int bidx = mt >> 2;          // batch of this m-tile
    const int tid = threadIdx.x;
    const int lane = tid & 31;
    const int wid  = tid >> 5;
    const int warpM = wid >> 2;
    const int warpN = wid & 3;

    if (tid < 128) bias_s[tid] = g_clsw[bidx * NOUT + n0 + tid];

    const __nv_bfloat16* gA = g_hidden + (size_t)m0 * HH;
    const __nv_bfloat16* gB = g_wbf    + (size_t)n0 * HH;

    auto load_chunk = [&](int st, int ck) {
        const __nv_bfloat16* ga = gA + ck * CHKK;
        const __nv_bfloat16* gb = gB + ck * CHKK;
#pragma unroll
        for (int i = 0; i < 4; i++) {
            int id  = i * 256 + tid;           // 0..1023
            int row = id >> 3, seg = id & 7;   // 128 rows x 8 16B-segs
            uint32_t sw = dswz(row, seg * 16);
            cp_async16(sA + st * STG16 + sw, ga + (size_t)row * HH + seg * 8);
            cp_async16(sB + st * STG16 + sw, gb + (size_t)row * HH + seg * 8);
        }
        cp_commit();
    };

    float acc[4][4][4];
#pragma unroll
    for (int i = 0; i < 4; i++)
#pragma unroll
        for (int j = 0; j < 4; j++)
#pragma unroll
            for (int r = 0; r < 4; r++) acc[i][j][r] = 0.0f;

#pragma unroll
    for (int s = 0; s < NST; s++) load_chunk(s, s);

    const int NCH = HH / CHKK;   // 12
    for (int k = 0; k < NCH; k++) {
        const int st = k % NST;
        asm volatile("cp.async.wait_group 2;\n" ::: "memory");
        __syncthreads();

        const uint32_t aS = sA + st * STG16;
        const uint32_t bS = sB + st * STG16;
#pragma unroll
        for (int kstep = 0; kstep < 4; kstep++) {
            const int colb = kstep * 32 + (lane >> 4) * 16;
            uint32_t areg[4][4], breg[4][2];
#pragma unroll
            for (int mi = 0; mi < 4; mi++)
                ldsm4(areg[mi], aS + dswz(warpM * 64 + mi * 16 + (lane & 15), colb));
#pragma unroll
            for (int jp = 0; jp < 2; jp++) {
                uint32_t t4[4];
                ldsm4(t4, bS + dswz(warpN * 32 + jp * 16 + (lane & 15), colb));
                breg[jp * 2][0]     = t4[0];
                breg[jp * 2 + 1][0] = t4[1];
                breg[jp * 2][1]     = t4[2];
                breg[jp * 2 + 1][1] = t4[3];
            }
#pragma unroll
            for (int mi = 0; mi < 4; mi++)
#pragma unroll
                for (int j = 0; j < 4; j++)
                    mma16816(acc[mi][j], areg[mi], breg[j]);
        }

        if (k + NST < NCH) {
            __syncthreads();               // all reads of stage st complete
            load_chunk(st, k + NST);
        } else {
            cp_commit();                   // keep wait_group accounting exact
        }
    }

    // ---- epilogue: ext-bias + RoPE, bf16 store -----------------------------
    const int g = lane >> 2, q = lane & 3;
#pragma unroll
    for (int mi = 0; mi < 4; mi++) {
#pragma unroll
        for (int h = 0; h < 2; h++) {
            int m = m0 + warpM * 64 + mi * 16 + h * 8 + g;
            int s = m & 511;
            size_t obase = (((size_t)(bidx * ENT + e)) * SS + s) * 128;
#pragma unroll
            for (int j = 0; j < 4; j++) {
                int c = warpN * 32 + j * 8 + 2 * q;
                float x = acc[mi][j][h * 2]     + bias_s[c];
                float y = acc[mi][j][h * 2 + 1] + bias_s[c + 1];
                int t = (c & 63) >> 1;
                float2 rc = g_rope[s * 32 + t];
                float rx = x * rc.x - y * rc.y;
                float ry = y * rc.x + x * rc.y;
                __nv_bfloat162 p = __floats2bfloat162_rn(rx, ry);
                *(uint32_t*)(g_qk + obase + c) = *(uint32_t*)&p;
            }
        }
    }
}

// ---------------------------------------------------------------------------
// Kernel 3: logits via mma.sync bf16 + causal-tile skip + streaming stores.
// (validated: 102 us, near memory floor — unchanged)
// ---------------------------------------------------------------------------
#define QROWB 144
#define DSMEM_LOG (2 * 128 * QROWB)

__global__ __launch_bounds__(256) void logits_kernel(const float* __restrict__ mask,
                                                     float* __restrict__ out)
{
    extern __shared__ char lsm[];
    const uint32_t sQ = smem_u32(lsm);
    const uint32_t sK = sQ + 128 * QROWB;

    const int e = blockIdx.y;
    const int b = blockIdx.z;
    const int mt = blockIdx.x >> 2, nt = blockIdx.x & 3;
    const int m0 = mt * 128, n0 = nt * 128;
    const int tid = threadIdx.x;

    const size_t rowbase = ((size_t)(b * ENT + e)) * SS;

    if (mt > nt) {
        int cg = (tid & 31) * 4;
        float4 v;
        {
            float p0 = mask[b * SS + n0 + cg];
            float p1 = mask[b * SS + n0 + cg + 1];
            float p2 = mask[b * SS + n0 + cg + 2];
            float p3 = mask[b * SS + n0 + cg + 3];
            v = make_float4(((p0 - 1.0f) * BIGF - BIGF) * 0.125f,
                            ((p1 - 1.0f) * BIGF - BIGF) * 0.125f,
                            ((p2 - 1.0f) * BIGF - BIGF) * 0.125f,
                            ((p3 - 1.0f) * BIGF - BIGF) * 0.125f);
        }
        for (int r = tid >> 5; r < 128; r += 8)
            __stcs((float4*)(out + (rowbase + m0 + r) * SS + n0 + cg), v);
        return;
    }

    const int lane = tid & 31;
    const int wid  = tid >> 5;
    const int warpM = wid >> 2;
    const int warpN = wid & 3;

#pragma unroll
    for (int i = 0; i < 4; i++) {
        int id  = tid * 4 + i;
        int row = id >> 3, seg = id & 7;
        uint32_t off = (uint32_t)(row * QROWB + seg * 16);
        cp_async16(sQ + off, g_qk + (rowbase + m0 + row) * 128 + seg * 8);
        cp_async16(sK + off, g_qk + (rowbase + n0 + row) * 128 + 64 + seg * 8);
    }
    cp_commit();
    asm volatile("cp.async.wait_group 0;\n" ::: "memory");
    __syncthreads();

    float acc[4][4][4];
#pragma unroll
    for (int i = 0; i < 4; i++)
#pragma unroll
        for (int j = 0; j < 4; j++)
#pragma unroll
            for (int r = 0; r < 4; r++) acc[i][j][r] = 0.0f;

#pragma unroll
    for (int kstep = 0; kstep < 4; kstep++) {
        uint32_t areg[4][4], breg[4][2];
#pragma unroll
        for (int mi = 0; mi < 4; mi++)
            ldsm4(areg[mi], sQ + (uint32_t)((warpM * 64 + mi * 16 + (lane & 15)) * QROWB
                                            + kstep * 32 + (lane >> 4) * 16));
#pragma unroll
        for (int jp = 0; jp < 2; jp++) {
            uint32_t t4[4];
            ldsm4(t4, sK + (uint32_t)((warpN * 32 + jp * 16 + (lane & 15)) * QROWB
                                      + kstep * 32 + (lane >> 4) * 16));
            breg[jp * 2][0]     = t4[0];
            breg[jp * 2 + 1][0] = t4[1];
            breg[jp * 2][1]     = t4[2];
            breg[jp * 2 + 1][1] = t4[3];
        }
#pragma unroll
        for (int mi = 0; mi < 4; mi++)
#pragma unroll
            for (int j = 0; j < 4; j++)
                mma16816(acc[mi][j], areg[mi], breg[j]);
    }

    const int g = lane >> 2, q = lane & 3;
    const int nbase = n0 + warpN * 32;
    float p0[4], p1[4];
#pragma unroll
    for (int j = 0; j < 4; j++) {
        int c = nbase + j * 8 + 2 * q;
        p0[j] = mask[b * SS + c];
        p1[j] = mask[b * SS + c + 1];
    }

#pragma unroll
    for (int mi = 0; mi < 4; mi++) {
#pragma unroll
        for (int h = 0; h < 2; h++) {
            int m = m0 + warpM * 64 + mi * 16 + h * 8 + g;
            size_t orow = (rowbase + m) * SS;
#pragma unroll
            for (int j = 0; j < 4; j++) {
                int c = nbase + j * 8 + 2 * q;
                float x = acc[mi][j][h * 2];
                float y = acc[mi][j][h * 2 + 1];
                x = x * p0[j] - (1.0f - p0[j]) * BIGF;
                y = y * p1[j] - (1.0f - p1[j]) * BIGF;
                if (m > c)     x -= BIGF;
                if (m > c + 1) y -= BIGF;
                __stcs((float2*)(out + orow + c), make_float2(x * 0.125f, y * 0.125f));
            }
        }
    }
}

// ---------------------------------------------------------------------------
extern "C" void kernel_launch(void* const* d_in, const int* in_sizes, int n_in,
                              void* d_out, int out_size)
{
    const float* lhs    = (const float*)d_in[0];
    const float* cls    = (const float*)d_in[1];
    const float* h0     = (const float*)d_in[2];
    const float* mask   = (const float*)d_in[3];
    const float* w_ih_f = (const float*)d_in[4];
    const float* w_hh_f = (const float*)d_in[5];
    const float* b_ih_f = (const float*)d_in[6];
    const float* b_hh_f = (const float*)d_in[7];
    const float* w_ih_b = (const float*)d_in[8];
    const float* w_hh_b = (const float*)d_in[9];
    const float* b_ih_b = (const float*)d_in[10];
    const float* b_hh_b = (const float*)d_in[11];
    const float* dw     = (const float*)d_in[12];
    const float* db     = (const float*)d_in[13];
    float* out = (float*)d_out;

    cudaFuncSetAttribute(dense_mma_kernel, cudaFuncAttributeMaxDynamicSharedMemorySize, DSMEM_DENSE);
    cudaFuncSetAttribute(logits_kernel,    cudaFuncAttributeMaxDynamicSharedMemorySize, DSMEM_LOG);

    prep_kernel<<<PREPB, 256>>>(dw, lhs, cls, h0, w_ih_f, w_hh_f, b_ih_f, b_hh_f,
                                w_ih_b, w_hh_b, b_ih_b, b_hh_b);
    clsw_kernel<<<NOUT / 256, 256>>>(dw, db);

    dense_mma_kernel<<<dim3(ENT, MDIM / 128), 256, DSMEM_DENSE>>>();

    logits_kernel<<<dim3(16, ENT, BB), 256, DSMEM_LOG>>>(mask, out);
}

// round 8
// speedup vs baseline: 1.5173x; 1.0496x over previous
#include <cuda_runtime.h>
#include <cuda_bf16.h>
#include <math.h>
#include <stdint.h>

#define ENT   52
#define INNER 64
#define BB    8
#define SS    512
#define HH    768
#define NOUT  6656    /* ENT*2*INNER */
#define KDIM  1536
#define MDIM  4096    /* BB*SS */
#define BIGF  1000000000000.0f
#define BLKB  16384   /* one 128x64 bf16 swizzled block */

// ---------------- scratch (device globals; no allocations allowed) ----------
__device__ float g_cls_emb[BB * HH];
__device__ float g_clsw[BB * NOUT];
// block layouts: [tile][chunk] of 16KB XOR-swizzled 128x64-bf16 blocks
__device__ __align__(16) uint8_t g_hidden_blk[(size_t)32 * 12 * BLKB];        // 6.3 MB
__device__ __align__(16) uint8_t g_wbf_blk[(size_t)ENT * 12 * BLKB];          // 10.2 MB
// g_qk blocks: [b][e][q/k][stile] -> 16KB block (128 rows x 64 cols bf16)
__device__ __align__(16) uint8_t g_qk_blk[(size_t)BB * ENT * 2 * 4 * BLKB];   // 54.5 MB
__device__ float2 g_rope[SS * 32];

// ---------------- PTX helpers ----------------------------------------------
__device__ __forceinline__ uint32_t smem_u32(const void* p) {
    uint32_t a;
    asm("{ .reg .u64 t; cvta.to.shared.u64 t, %1; cvt.u32.u64 %0, t; }" : "=r"(a) : "l"(p));
    return a;
}
__device__ __forceinline__ void mbar_init(uint32_t a, uint32_t n) {
    asm volatile("mbarrier.init.shared.b64 [%0], %1;" :: "r"(a), "r"(n) : "memory");
}
__device__ __forceinline__ void mbar_expect(uint32_t a, uint32_t tx) {
    asm volatile("mbarrier.arrive.expect_tx.shared.b64 _, [%0], %1;" :: "r"(a), "r"(tx) : "memory");
}
__device__ __forceinline__ void mbar_wait(uint32_t a, uint32_t ph) {
    asm volatile("{\n\t.reg .pred P;\n\t"
                 "LW_%=:\n\t"
                 "mbarrier.try_wait.parity.shared.b64 P, [%0], %1;\n\t"
                 "@!P bra LW_%=;\n\t}"
                 :: "r"(a), "r"(ph) : "memory");
}
__device__ __forceinline__ void bulk_cp(uint32_t dst, const void* src, uint32_t bytes,
                                        uint32_t mbar) {
    asm volatile("cp.async.bulk.shared::cta.global.mbarrier::complete_tx::bytes "
                 "[%0], [%1], %2, [%3];"
                 :: "r"(dst), "l"(src), "r"(bytes), "r"(mbar) : "memory");
}
__device__ __forceinline__ void ldsm4(uint32_t* r, uint32_t addr) {
    asm volatile("ldmatrix.sync.aligned.m8n8.x4.shared.b16 {%0,%1,%2,%3}, [%4];"
                 : "=r"(r[0]), "=r"(r[1]), "=r"(r[2]), "=r"(r[3]) : "r"(addr));
}
__device__ __forceinline__ void mma16816(float* c, const uint32_t* a, const uint32_t* b) {
    asm volatile(
        "mma.sync.aligned.m16n8k16.row.col.f32.bf16.bf16.f32 "
        "{%0,%1,%2,%3}, {%4,%5,%6,%7}, {%8,%9}, {%0,%1,%2,%3};"
        : "+f"(c[0]), "+f"(c[1]), "+f"(c[2]), "+f"(c[3])
        : "r"(a[0]), "r"(a[1]), "r"(a[2]), "r"(a[3]), "r"(b[0]), "r"(b[1]));
}
__device__ __forceinline__ uint32_t dswz(int row, int colb) {
    return (uint32_t)(row * 128 + (colb ^ ((row & 7) << 4)));
}

// ---------------------------------------------------------------------------
// Kernel 1 (fused prep): W1 -> swizzled blocks, lhs -> swizzled blocks,
// rope table, GRU cells. All independent, one launch.
// ---------------------------------------------------------------------------
#define CONVB (NOUT * HH / 4 / 256)    /* 4992 */
#define BHB   (MDIM * HH / 4 / 256)    /* 3072 */
#define ROPEB 64
#define GRUB  24
#define PREPB (CONVB + BHB + ROPEB + GRUB)

__global__ __launch_bounds__(256) void prep_kernel(
    const float* __restrict__ dw, const float* __restrict__ lhs,
    const float* __restrict__ cls, const float* __restrict__ h0,
    const float* __restrict__ w_ih_f, const float* __restrict__ w_hh_f,
    const float* __restrict__ b_ih_f, const float* __restrict__ b_hh_f,
    const float* __restrict__ w_ih_b, const float* __restrict__ w_hh_b,
    const float* __restrict__ b_ih_b, const float* __restrict__ b_hh_b)
{
    const int bid = blockIdx.x;

    if (bid < CONVB) {
        // ---- W1 fp32 -> bf16, swizzled block layout ----
        int i = bid * 256 + threadIdx.x;
        int n  = i / 192;
        int kq = (i % 192) * 4;
        float4 v = *(const float4*)(dw + (size_t)n * KDIM + kq);
        __nv_bfloat162 p0 = __floats2bfloat162_rn(v.x, v.y);
        __nv_bfloat162 p1 = __floats2bfloat162_rn(v.z, v.w);
        uint2 o; o.x = *(uint32_t*)&p0; o.y = *(uint32_t*)&p1;
        int e = n >> 7, row = n & 127, ch = kq >> 6, kc = kq & 63;
        size_t off = (size_t)(e * 12 + ch) * BLKB + dswz(row, (kc >> 3) << 4) + (kc & 7) * 2;
        *(uint2*)(g_wbf_blk + off) = o;
        return;
    }
    if (bid < CONVB + BHB) {
        // ---- lhs fp32 -> bf16, swizzled block layout ----
        size_t gid = (size_t)(bid - CONVB) * 256 + threadIdx.x;
        size_t i = gid * 4;
        float4 v = *(const float4*)(lhs + i);
        __nv_bfloat162 p0 = __floats2bfloat162_rn(v.x, v.y);
        __nv_bfloat162 p1 = __floats2bfloat162_rn(v.z, v.w);
        uint2 o; o.x = *(uint32_t*)&p0; o.y = *(uint32_t*)&p1;
        int m = (int)(i / HH), k = (int)(i % HH);
        int mt = m >> 7, row = m & 127, ch = k >> 6, kc = k & 63;
        size_t off = (size_t)(mt * 12 + ch) * BLKB + dswz(row, (kc >> 3) << 4) + (kc & 7) * 2;
        *(uint2*)(g_hidden_blk + off) = o;
        return;
    }
    if (bid < CONVB + BHB + ROPEB) {
        int idx = (bid - CONVB - BHB) * 256 + threadIdx.x;
        int s = idx >> 5, t = idx & 31;
        float invf = powf(10000.0f, -2.0f * (float)t / 64.0f);
        float sn, cs;
        sincosf((float)s * invf, &sn, &cs);
        g_rope[idx] = make_float2(cs, sn);
        return;
    }

    // ---- GRU ----
    const int gid = bid - (CONVB + BHB + ROPEB);
    const int dir = gid / 12;
    const int u   = (gid % 12) * 32 + (threadIdx.x >> 3);
    const int b   = threadIdx.x & 7;

    const float* w_ih = dir ? w_ih_b : w_ih_f;
    const float* w_hh = dir ? w_hh_b : w_hh_f;
    const float* b_ih = dir ? b_ih_b : b_ih_f;
    const float* b_hh = dir ? b_hh_b : b_hh_f;

    __shared__ float xs[BB][HH + 4];
    __shared__ float hs[BB][384 + 4];

    for (int i = threadIdx.x; i < BB * HH; i += blockDim.x)
        xs[i / HH][i % HH] = cls[i];
    for (int i = threadIdx.x; i < BB * 384; i += blockDim.x)
        hs[i / 384][i % 384] = h0[(size_t)dir * BB * 384 + i];
    __syncthreads();

    float gi[3], gh[3];
#pragma unroll
    for (int g = 0; g < 3; g++) {
        const float* w = w_ih + (size_t)(g * 384 + u) * HH;
        float acc = b_ih[g * 384 + u];
#pragma unroll 4
        for (int k = 0; k < HH; k += 4) {
            float4 wv = *(const float4*)(w + k);
            acc += wv.x * xs[b][k] + wv.y * xs[b][k + 1] + wv.z * xs[b][k + 2] + wv.w * xs[b][k + 3];
        }
        gi[g] = acc;
        const float* w2 = w_hh + (size_t)(g * 384 + u) * 384;
        float acc2 = b_hh[g * 384 + u];
#pragma unroll 4
        for (int k = 0; k < 384; k += 4) {
            float4 wv = *(const float4*)(w2 + k);
            acc2 += wv.x * hs[b][k] + wv.y * hs[b][k + 1] + wv.z * hs[b][k + 2] + wv.w * hs[b][k + 3];
        }
        gh[g] = acc2;
    }
    float r = 1.0f / (1.0f + expf(-(gi[0] + gh[0])));
    float z = 1.0f / (1.0f + expf(-(gi[1] + gh[1])));
    float n = tanhf(gi[2] + r * gh[2]);
    g_cls_emb[b * HH + dir * 384 + u] = (1.0f - z) * n + z * hs[b][u];
}

// ---------------------------------------------------------------------------
// Kernel 1b: extended bias  clsw[b][n] = db[n] + cls_emb[b,:] . W2[n,:]
// ---------------------------------------------------------------------------
__global__ __launch_bounds__(256) void clsw_kernel(const float* __restrict__ dw,
                                                   const float* __restrict__ db)
{
    __shared__ float cl[BB][HH + 4];
    for (int i = threadIdx.x; i < BB * HH; i += 256)
        cl[i / HH][i % HH] = g_cls_emb[i];
    __syncthreads();

    const int n = blockIdx.x * 256 + threadIdx.x;
    const float* w = dw + (size_t)n * KDIM + HH;
    float acc[BB];
#pragma unroll
    for (int b = 0; b < BB; b++) acc[b] = 0.0f;
#pragma unroll 4
    for (int k = 0; k < HH; k += 4) {
        float4 wv = *(const float4*)(w + k);
#pragma unroll
        for (int b = 0; b < BB; b++)
            acc[b] += wv.x * cl[b][k] + wv.y * cl[b][k + 1]
                    + wv.z * cl[b][k + 2] + wv.w * cl[b][k + 3];
    }
    float bias = db[n];
#pragma unroll
    for (int b = 0; b < BB; b++) g_clsw[b * NOUT + n] = acc[b] + bias;
}

// ---------------------------------------------------------------------------
// Kernel 2: dense GEMM, bulk-copy (TMA-class) pipeline. CTA 128x128x64,
// 8 warps (2Mx4N), 3 stages, mbarrier expect_tx. Epilogue: bias + RoPE ->
// swizzled g_qk blocks. grid (52, 32), 256 threads, occ 2.
// ---------------------------------------------------------------------------
#define NST   3
#define DSMEM_DENSE (NST * 2 * BLKB)   /* 98304 */

__global__ __launch_bounds__(256, 2) void dense_mma_kernel()
{
    extern __shared__ char dsm[];
    const uint32_t sBase = smem_u32(dsm);       // stage st: A at st*32768, B at +16384
    __shared__ uint64_t mbv[NST];
    __shared__ float bias_s[128];
    const uint32_t mb0 = smem_u32(mbv);

    const int e  = blockIdx.x;
    const int mt = blockIdx.y;
    const int m0 = mt * 128;
    const int n0 = e * 128;
    const int bidx = mt >> 2;
    const int stile = mt & 3;
    const int tid = threadIdx.x;
    const int lane = tid & 31;
    const int wid  = tid >> 5;
    const int warpM = wid >> 2;
    const int warpN = wid & 3;

    if (tid < 128) bias_s[tid] = g_clsw[bidx * NOUT + n0 + tid];
    if (tid == 0) {
#pragma unroll
        for (int s = 0; s < NST; s++) mbar_init(mb0 + s * 8, 1);
    }
    __syncthreads();

    const uint8_t* gA = g_hidden_blk + (size_t)mt * 12 * BLKB;
    const uint8_t* gB = g_wbf_blk    + (size_t)e  * 12 * BLKB;

    if (tid == 0) {
#pragma unroll
        for (int s = 0; s < NST; s++) {
            mbar_expect(mb0 + s * 8, 2 * BLKB);
            bulk_cp(sBase + s * 2 * BLKB,        gA + (size_t)s * BLKB, BLKB, mb0 + s * 8);
            bulk_cp(sBase + s * 2 * BLKB + BLKB, gB + (size_t)s * BLKB, BLKB, mb0 + s * 8);
        }
    }

    float acc[4][4][4];
#pragma unroll
    for (int i = 0; i < 4; i++)
#pragma unroll
        for (int j = 0; j < 4; j++)
#pragma unroll
            for (int r = 0; r < 4; r++) acc[i][j][r] = 0.0f;

    const int NCH = 12;
    for (int k = 0; k < NCH; k++) {
        const int st = k % NST;
        mbar_wait(mb0 + st * 8, (uint32_t)((k / NST) & 1));

        const uint32_t aS = sBase + st * 2 * BLKB;
        const uint32_t bS = aS + BLKB;
#pragma unroll
        for (int kstep = 0; kstep < 4; kstep++) {
            const int colb = kstep * 32 + (lane >> 4) * 16;
            uint32_t areg[4][4], breg[4][2];
#pragma unroll
            for (int mi = 0; mi < 4; mi++)
                ldsm4(areg[mi], aS + dswz(warpM * 64 + mi * 16 + (lane & 15), colb));
#pragma unroll
            for (int jp = 0; jp < 2; jp++) {
                uint32_t t4[4];
                ldsm4(t4, bS + dswz(warpN * 32 + jp * 16 + (lane & 15), colb));
                breg[jp * 2][0]     = t4[0];
                breg[jp * 2 + 1][0] = t4[1];
                breg[jp * 2][1]     = t4[2];
                breg[jp * 2 + 1][1] = t4[3];
            }
#pragma unroll
            for (int mi = 0; mi < 4; mi++)
#pragma unroll
                for (int j = 0; j < 4; j++)
                    mma16816(acc[mi][j], areg[mi], breg[j]);
        }

        __syncthreads();            // all warps done reading stage st
        if (tid == 0 && k + NST < NCH) {
            mbar_expect(mb0 + st * 8, 2 * BLKB);
            bulk_cp(sBase + st * 2 * BLKB,        gA + (size_t)(k + NST) * BLKB, BLKB, mb0 + st * 8);
            bulk_cp(sBase + st * 2 * BLKB + BLKB, gB + (size_t)(k + NST) * BLKB, BLKB, mb0 + st * 8);
        }
    }

    // ---- epilogue: ext-bias + RoPE -> swizzled g_qk blocks -----------------
    const int g = lane >> 2, q = lane & 3;
#pragma unroll
    for (int mi = 0; mi < 4; mi++) {
#pragma unroll
        for (int h = 0; h < 2; h++) {
            int row = warpM * 64 + mi * 16 + h * 8 + g;      // 0..127
            int s = (m0 + row) & 511;
#pragma unroll
            for (int j = 0; j < 4; j++) {
                int c = warpN * 32 + j * 8 + 2 * q;          // 0..126 even
                float x = acc[mi][j][h * 2]     + bias_s[c];
                float y = acc[mi][j][h * 2 + 1] + bias_s[c + 1];
                int t = (c & 63) >> 1;
                float2 rc = g_rope[s * 32 + t];
                float rx = x * rc.x - y * rc.y;
                float ry = y * rc.x + x * rc.y;
                __nv_bfloat162 p = __floats2bfloat162_rn(rx, ry);
                int qk = c >> 6, col = c & 63;
                size_t blk = ((size_t)(bidx * ENT + e) * 2 + qk) * 4 + stile;
                size_t off = blk * BLKB + dswz(row, (col >> 3) << 4) + (col & 7) * 2;
                *(uint32_t*)(g_qk_blk + off) = *(uint32_t*)&p;
            }
        }
    }
}

// ---------------------------------------------------------------------------
// Kernel 3: logits, bulk-copy loads + mma.sync + causal skip + streaming st.
// grid (16, 52, 8), 256 threads.
// ---------------------------------------------------------------------------
#define DSMEM_LOG (2 * BLKB)

__global__ __launch_bounds__(256) void logits_kernel(const float* __restrict__ mask,
                                                     float* __restrict__ out)
{
    extern __shared__ char lsm[];
    const uint32_t sQ = smem_u32(lsm);
    const uint32_t sK = sQ + BLKB;
    __shared__ uint64_t mbv;
    const uint32_t mb = smem_u32(&mbv);

    const int e = blockIdx.y;
    const int b = blockIdx.z;
    const int mt = blockIdx.x >> 2, nt = blockIdx.x & 3;
    const int m0 = mt * 128, n0 = nt * 128;
    const int tid = threadIdx.x;

    const size_t rowbase = ((size_t)(b * ENT + e)) * SS;

    if (mt > nt) {
        int cg = (tid & 31) * 4;
        float4 v;
        {
            float p0 = mask[b * SS + n0 + cg];
            float p1 = mask[b * SS + n0 + cg + 1];
            float p2 = mask[b * SS + n0 + cg + 2];
            float p3 = mask[b * SS + n0 + cg + 3];
            v = make_float4(((p0 - 1.0f) * BIGF - BIGF) * 0.125f,
                            ((p1 - 1.0f) * BIGF - BIGF) * 0.125f,
                            ((p2 - 1.0f) * BIGF - BIGF) * 0.125f,
                            ((p3 - 1.0f) * BIGF - BIGF) * 0.125f);
        }
        for (int r = tid >> 5; r < 128; r += 8)
            __stcs((float4*)(out + (rowbase + m0 + r) * SS + n0 + cg), v);
        return;
    }

    if (tid == 0) mbar_init(mb, 1);
    __syncthreads();
    if (tid == 0) {
        size_t base = (size_t)(b * ENT + e) * 2;
        mbar_expect(mb, 2 * BLKB);
        bulk_cp(sQ, g_qk_blk + (base * 4 + mt) * BLKB,       BLKB, mb);
        bulk_cp(sK, g_qk_blk + ((base + 1) * 4 + nt) * BLKB, BLKB, mb);
    }

    const int lane = tid & 31;
    const int wid  = tid >> 5;
    const int warpM = wid >> 2;
    const int warpN = wid & 3;

    mbar_wait(mb, 0u);

    float acc[4][4][4];
#pragma unroll
    for (int i = 0; i < 4; i++)
#pragma unroll
        for (int j = 0; j < 4; j++)
#pragma unroll
            for (int r = 0; r < 4; r++) acc[i][j][r] = 0.0f;

#pragma unroll
    for (int kstep = 0; kstep < 4; kstep++) {
        const int colb = kstep * 32 + (lane >> 4) * 16;
        uint32_t areg[4][4], breg[4][2];
#pragma unroll
        for (int mi = 0; mi < 4; mi++)
            ldsm4(areg[mi], sQ + dswz(warpM * 64 + mi * 16 + (lane & 15), colb));
#pragma unroll
        for (int jp = 0; jp < 2; jp++) {
            uint32_t t4[4];
            ldsm4(t4, sK + dswz(warpN * 32 + jp * 16 + (lane & 15), colb));
            breg[jp * 2][0]     = t4[0];
            breg[jp * 2 + 1][0] = t4[1];
            breg[jp * 2][1]     = t4[2];
            breg[jp * 2 + 1][1] = t4[3];
        }
#pragma unroll
        for (int mi = 0; mi < 4; mi++)
#pragma unroll
            for (int j = 0; j < 4; j++)
                mma16816(acc[mi][j], areg[mi], breg[j]);
    }

    const int g = lane >> 2, q = lane & 3;
    const int nbase = n0 + warpN * 32;
    float p0[4], p1[4];
#pragma unroll
    for (int j = 0; j < 4; j++) {
        int c = nbase + j * 8 + 2 * q;
        p0[j] = mask[b * SS + c];
        p1[j] = mask[b * SS + c + 1];
    }

#pragma unroll
    for (int mi = 0; mi < 4; mi++) {
#pragma unroll
        for (int h = 0; h < 2; h++) {
            int m = m0 + warpM * 64 + mi * 16 + h * 8 + g;
            size_t orow = (rowbase + m) * SS;
#pragma unroll
            for (int j = 0; j < 4; j++) {
                int c = nbase + j * 8 + 2 * q;
                float x = acc[mi][j][h * 2];
                float y = acc[mi][j][h * 2 + 1];
                x = x * p0[j] - (1.0f - p0[j]) * BIGF;
                y = y * p1[j] - (1.0f - p1[j]) * BIGF;
                if (m > c)     x -= BIGF;
                if (m > c + 1) y -= BIGF;
                __stcs((float2*)(out + orow + c), make_float2(x * 0.125f, y * 0.125f));
            }
        }
    }
}

// ---------------------------------------------------------------------------
extern "C" void kernel_launch(void* const* d_in, const int* in_sizes, int n_in,
                              void* d_out, int out_size)
{
    const float* lhs    = (const float*)d_in[0];
    const float* cls    = (const float*)d_in[1];
    const float* h0     = (const float*)d_in[2];
    const float* mask   = (const float*)d_in[3];
    const float* w_ih_f = (const float*)d_in[4];
    const float* w_hh_f = (const float*)d_in[5];
    const float* b_ih_f = (const float*)d_in[6];
    const float* b_hh_f = (const float*)d_in[7];
    const float* w_ih_b = (const float*)d_in[8];
    const float* w_hh_b = (const float*)d_in[9];
    const float* b_ih_b = (const float*)d_in[10];
    const float* b_hh_b = (const float*)d_in[11];
    const float* dw     = (const float*)d_in[12];
    const float* db     = (const float*)d_in[13];
    float* out = (float*)d_out;

    cudaFuncSetAttribute(dense_mma_kernel, cudaFuncAttributeMaxDynamicSharedMemorySize, DSMEM_DENSE);
    cudaFuncSetAttribute(logits_kernel,    cudaFuncAttributeMaxDynamicSharedMemorySize, DSMEM_LOG);

    prep_kernel<<<PREPB, 256>>>(dw, lhs, cls, h0, w_ih_f, w_hh_f, b_ih_f, b_hh_f,
                                w_ih_b, w_hh_b, b_ih_b, b_hh_b);
    clsw_kernel<<<NOUT / 256, 256>>>(dw, db);

    dense_mma_kernel<<<dim3(ENT, MDIM / 128), 256, DSMEM_DENSE>>>();

    logits_kernel<<<dim3(16, ENT, BB), 256, DSMEM_LOG>>>(mask, out);
}

// round 9
// speedup vs baseline: 1.6759x; 1.1046x over previous
#include <cuda_runtime.h>
#include <cuda_bf16.h>
#include <cuda_fp8.h>
#include <math.h>
#include <stdint.h>

#define ENT   52
#define INNER 64
#define BB    8
#define SS    512
#define HH    768
#define NOUT  6656    /* ENT*2*INNER */
#define KDIM  1536
#define MDIM  4096    /* BB*SS */
#define BIGF  1000000000000.0f
#define BLKB  16384   /* one 16KB swizzled block */
#define WSCALE 32.0f
#define WISCALE (1.0f / 32.0f)

// ---------------- scratch (device globals; no allocations allowed) ----------
__device__ float g_cls_emb[BB * HH];
__device__ float g_clsw[BB * NOUT];
// fp8 operand blocks: [tile][chunk] of 16KB XOR-swizzled 128row x 128col-fp8
__device__ __align__(16) uint8_t g_hidden_blk[(size_t)32 * 6 * BLKB];         // 3.1 MB
__device__ __align__(16) uint8_t g_wbf_blk[(size_t)ENT * 6 * BLKB];           // 5.1 MB
// g_qk blocks (bf16): [b][e][q/k][stile] -> 16KB block (128 rows x 64 cols)
__device__ __align__(16) uint8_t g_qk_blk[(size_t)BB * ENT * 2 * 4 * BLKB];   // 54.5 MB
__device__ float2 g_rope[SS * 32];

// ---------------- PTX helpers ----------------------------------------------
__device__ __forceinline__ uint32_t smem_u32(const void* p) {
    uint32_t a;
    asm("{ .reg .u64 t; cvta.to.shared.u64 t, %1; cvt.u32.u64 %0, t; }" : "=r"(a) : "l"(p));
    return a;
}
__device__ __forceinline__ void mbar_init(uint32_t a, uint32_t n) {
    asm volatile("mbarrier.init.shared.b64 [%0], %1;" :: "r"(a), "r"(n) : "memory");
}
__device__ __forceinline__ void mbar_expect(uint32_t a, uint32_t tx) {
    asm volatile("mbarrier.arrive.expect_tx.shared.b64 _, [%0], %1;" :: "r"(a), "r"(tx) : "memory");
}
__device__ __forceinline__ void mbar_wait(uint32_t a, uint32_t ph) {
    asm volatile("{\n\t.reg .pred P;\n\t"
                 "LW_%=:\n\t"
                 "mbarrier.try_wait.parity.shared.b64 P, [%0], %1;\n\t"
                 "@!P bra LW_%=;\n\t}"
                 :: "r"(a), "r"(ph) : "memory");
}
__device__ __forceinline__ void bulk_cp(uint32_t dst, const void* src, uint32_t bytes,
                                        uint32_t mbar) {
    asm volatile("cp.async.bulk.shared::cta.global.mbarrier::complete_tx::bytes "
                 "[%0], [%1], %2, [%3];"
                 :: "r"(dst), "l"(src), "r"(bytes), "r"(mbar) : "memory");
}
__device__ __forceinline__ void ldsm4(uint32_t* r, uint32_t addr) {
    asm volatile("ldmatrix.sync.aligned.m8n8.x4.shared.b16 {%0,%1,%2,%3}, [%4];"
                 : "=r"(r[0]), "=r"(r[1]), "=r"(r[2]), "=r"(r[3]) : "r"(addr));
}
__device__ __forceinline__ void mma16816(float* c, const uint32_t* a, const uint32_t* b) {
    asm volatile(
        "mma.sync.aligned.m16n8k16.row.col.f32.bf16.bf16.f32 "
        "{%0,%1,%2,%3}, {%4,%5,%6,%7}, {%8,%9}, {%0,%1,%2,%3};"
        : "+f"(c[0]), "+f"(c[1]), "+f"(c[2]), "+f"(c[3])
        : "r"(a[0]), "r"(a[1]), "r"(a[2]), "r"(a[3]), "r"(b[0]), "r"(b[1]));
}
__device__ __forceinline__ void mma16832f8(float* c, const uint32_t* a, const uint32_t* b) {
    asm volatile(
        "mma.sync.aligned.m16n8k32.row.col.f32.e4m3.e4m3.f32 "
        "{%0,%1,%2,%3}, {%4,%5,%6,%7}, {%8,%9}, {%0,%1,%2,%3};"
        : "+f"(c[0]), "+f"(c[1]), "+f"(c[2]), "+f"(c[3])
        : "r"(a[0]), "r"(a[1]), "r"(a[2]), "r"(a[3]), "r"(b[0]), "r"(b[1]));
}
__device__ __forceinline__ uint32_t dswz(int row, int colb) {
    return (uint32_t)(row * 128 + (colb ^ ((row & 7) << 4)));
}
__device__ __forceinline__ uint32_t fp8x4(float a, float b, float c, float d) {
    __nv_fp8x2_storage_t lo = __nv_cvt_float2_to_fp8x2(make_float2(a, b),
                                                       __NV_SATFINITE, __NV_E4M3);
    __nv_fp8x2_storage_t hi = __nv_cvt_float2_to_fp8x2(make_float2(c, d),
                                                       __NV_SATFINITE, __NV_E4M3);
    return (uint32_t)lo | ((uint32_t)hi << 16);
}

// ---------------------------------------------------------------------------
// Kernel 1 (fused prep): W1 -> fp8 blocks (x32), lhs -> fp8 blocks, rope,
// GRU cells. All independent, one launch.
// ---------------------------------------------------------------------------
#define CONVB (NOUT * HH / 4 / 256)    /* 4992 */
#define BHB   (MDIM * HH / 4 / 256)    /* 3072 */
#define ROPEB 64
#define GRUB  24
#define PREPB (CONVB + BHB + ROPEB + GRUB)

__global__ __launch_bounds__(256) void prep_kernel(
    const float* __restrict__ dw, const float* __restrict__ lhs,
    const float* __restrict__ cls, const float* __restrict__ h0,
    const float* __restrict__ w_ih_f, const float* __restrict__ w_hh_f,
    const float* __restrict__ b_ih_f, const float* __restrict__ b_hh_f,
    const float* __restrict__ w_ih_b, const float* __restrict__ w_hh_b,
    const float* __restrict__ b_ih_b, const float* __restrict__ b_hh_b)
{
    const int bid = blockIdx.x;

    if (bid < CONVB) {
        // ---- W1 fp32 -> fp8 (x32), swizzled block layout ----
        int i = bid * 256 + threadIdx.x;
        int n  = i / 192;
        int kq = (i % 192) * 4;
        float4 v = *(const float4*)(dw + (size_t)n * KDIM + kq);
        uint32_t w = fp8x4(v.x * WSCALE, v.y * WSCALE, v.z * WSCALE, v.w * WSCALE);
        int e = n >> 7, row = n & 127, ch = kq >> 7, kc = kq & 127;
        size_t off = (size_t)(e * 6 + ch) * BLKB + dswz(row, kc & 0x70) + (kc & 15);
        *(uint32_t*)(g_wbf_blk + off) = w;
        return;
    }
    if (bid < CONVB + BHB) {
        // ---- lhs fp32 -> fp8, swizzled block layout ----
        size_t gid = (size_t)(bid - CONVB) * 256 + threadIdx.x;
        size_t i = gid * 4;
        float4 v = *(const float4*)(lhs + i);
        uint32_t w = fp8x4(v.x, v.y, v.z, v.w);
        int m = (int)(i / HH), k = (int)(i % HH);
        int mt = m >> 7, row = m & 127, ch = k >> 7, kc = k & 127;
        size_t off = (size_t)(mt * 6 + ch) * BLKB + dswz(row, kc & 0x70) + (kc & 15);
        *(uint32_t*)(g_hidden_blk + off) = w;
        return;
    }
    if (bid < CONVB + BHB + ROPEB) {
        int idx = (bid - CONVB - BHB) * 256 + threadIdx.x;
        int s = idx >> 5, t = idx & 31;
        float invf = powf(10000.0f, -2.0f * (float)t / 64.0f);
        float sn, cs;
        sincosf((float)s * invf, &sn, &cs);
        g_rope[idx] = make_float2(cs, sn);
        return;
    }

    // ---- GRU ----
    const int gid = bid - (CONVB + BHB + ROPEB);
    const int dir = gid / 12;
    const int u   = (gid % 12) * 32 + (threadIdx.x >> 3);
    const int b   = threadIdx.x & 7;

    const float* w_ih = dir ? w_ih_b : w_ih_f;
    const float* w_hh = dir ? w_hh_b : w_hh_f;
    const float* b_ih = dir ? b_ih_b : b_ih_f;
    const float* b_hh = dir ? b_hh_b : b_hh_f;

    __shared__ float xs[BB][HH + 4];
    __shared__ float hs[BB][384 + 4];

    for (int i = threadIdx.x; i < BB * HH; i += blockDim.x)
        xs[i / HH][i % HH] = cls[i];
    for (int i = threadIdx.x; i < BB * 384; i += blockDim.x)
        hs[i / 384][i % 384] = h0[(size_t)dir * BB * 384 + i];
    __syncthreads();

    float gi[3], gh[3];
#pragma unroll
    for (int g = 0; g < 3; g++) {
        const float* w = w_ih + (size_t)(g * 384 + u) * HH;
        float acc = b_ih[g * 384 + u];
#pragma unroll 4
        for (int k = 0; k < HH; k += 4) {
            float4 wv = *(const float4*)(w + k);
            acc += wv.x * xs[b][k] + wv.y * xs[b][k + 1] + wv.z * xs[b][k + 2] + wv.w * xs[b][k + 3];
        }
        gi[g] = acc;
        const float* w2 = w_hh + (size_t)(g * 384 + u) * 384;
        float acc2 = b_hh[g * 384 + u];
#pragma unroll 4
        for (int k = 0; k < 384; k += 4) {
            float4 wv = *(const float4*)(w2 + k);
            acc2 += wv.x * hs[b][k] + wv.y * hs[b][k + 1] + wv.z * hs[b][k + 2] + wv.w * hs[b][k + 3];
        }
        gh[g] = acc2;
    }
    float r = 1.0f / (1.0f + expf(-(gi[0] + gh[0])));
    float z = 1.0f / (1.0f + expf(-(gi[1] + gh[1])));
    float n = tanhf(gi[2] + r * gh[2]);
    g_cls_emb[b * HH + dir * 384 + u] = (1.0f - z) * n + z * hs[b][u];
}

// ---------------------------------------------------------------------------
// Kernel 1b: extended bias, 4-way K-split. grid 104, 256 thr = 64 n x 4 kseg.
// ---------------------------------------------------------------------------
__global__ __launch_bounds__(256) void clsw_kernel(const float* __restrict__ dw,
                                                   const float* __restrict__ db)
{
    __shared__ float cl[BB][HH + 4];
    __shared__ float red[4][64][BB];
    for (int i = threadIdx.x; i < BB * HH; i += 256)
        cl[i / HH][i % HH] = g_cls_emb[i];
    __syncthreads();

    const int nl = threadIdx.x & 63;
    const int ks = threadIdx.x >> 6;          // 0..3
    const int n  = blockIdx.x * 64 + nl;
    const int k0 = ks * 192;

    const float* w = dw + (size_t)n * KDIM + HH + k0;
    float acc[BB];
#pragma unroll
    for (int b = 0; b < BB; b++) acc[b] = 0.0f;
#pragma unroll 4
    for (int k = 0; k < 192; k += 4) {
        float4 wv = *(const float4*)(w + k);
#pragma unroll
        for (int b = 0; b < BB; b++)
            acc[b] += wv.x * cl[b][k0 + k] + wv.y * cl[b][k0 + k + 1]
                    + wv.z * cl[b][k0 + k + 2] + wv.w * cl[b][k0 + k + 3];
    }
#pragma unroll
    for (int b = 0; b < BB; b++) red[ks][nl][b] = acc[b];
    __syncthreads();
    if (ks == 0) {
        float bias = db[n];
#pragma unroll
        for (int b = 0; b < BB; b++)
            g_clsw[b * NOUT + n] = red[0][nl][b] + red[1][nl][b] + red[2][nl][b]
                                 + red[3][nl][b] + bias;
    }
}

// ---------------------------------------------------------------------------
// Kernel 2: dense GEMM in fp8 e4m3 (m16n8k32), bulk-copy pipeline.
// CTA 128x128, K-chunk 128 (6 chunks), 3 stages, 8 warps (2Mx4N), occ 2.
// Epilogue: unscale + ext-bias + RoPE -> bf16 swizzled g_qk blocks.
// ---------------------------------------------------------------------------
#define NST   3
#define DSMEM_DENSE (NST * 2 * BLKB)   /* 98304 */

__global__ __launch_bounds__(256, 2) void dense_mma_kernel()
{
    extern __shared__ char dsm[];
    const uint32_t sBase = smem_u32(dsm);
    __shared__ uint64_t mbv[NST];
    __shared__ float bias_s[128];
    const uint32_t mb0 = smem_u32(mbv);

    const int e  = blockIdx.x;
    const int mt = blockIdx.y;
    const int m0 = mt * 128;
    const int n0 = e * 128;
    const int bidx = mt >> 2;
    const int stile = mt & 3;
    const int tid = threadIdx.x;
    const int lane = tid & 31;
    const int wid  = tid >> 5;
    const int warpM = wid >> 2;
    const int warpN = wid & 3;

    if (tid < 128) bias_s[tid] = g_clsw[bidx * NOUT + n0 + tid];
    if (tid == 0) {
#pragma unroll
        for (int s = 0; s < NST; s++) mbar_init(mb0 + s * 8, 1);
    }
    __syncthreads();

    const uint8_t* gA = g_hidden_blk + (size_t)mt * 6 * BLKB;
    const uint8_t* gB = g_wbf_blk    + (size_t)e  * 6 * BLKB;

    if (tid == 0) {
#pragma unroll
        for (int s = 0; s < NST; s++) {
            mbar_expect(mb0 + s * 8, 2 * BLKB);
            bulk_cp(sBase + s * 2 * BLKB,        gA + (size_t)s * BLKB, BLKB, mb0 + s * 8);
            bulk_cp(sBase + s * 2 * BLKB + BLKB, gB + (size_t)s * BLKB, BLKB, mb0 + s * 8);
        }
    }

    float acc[4][4][4];
#pragma unroll
    for (int i = 0; i < 4; i++)
#pragma unroll
        for (int j = 0; j < 4; j++)
#pragma unroll
            for (int r = 0; r < 4; r++) acc[i][j][r] = 0.0f;

    const int NCH = 6;
    for (int k = 0; k < NCH; k++) {
        const int st = k % NST;
        mbar_wait(mb0 + st * 8, (uint32_t)((k / NST) & 1));

        const uint32_t aS = sBase + st * 2 * BLKB;
        const uint32_t bS = aS + BLKB;
#pragma unroll
        for (int kstep = 0; kstep < 4; kstep++) {     // 32 fp8-K per step
            const int colb = kstep * 32 + (lane >> 4) * 16;
            uint32_t areg[4][4], breg[4][2];
#pragma unroll
            for (int mi = 0; mi < 4; mi++)
                ldsm4(areg[mi], aS + dswz(warpM * 64 + mi * 16 + (lane & 15), colb));
#pragma unroll
            for (int jp = 0; jp < 2; jp++) {
                uint32_t t4[4];
                ldsm4(t4, bS + dswz(warpN * 32 + jp * 16 + (lane & 15), colb));
                breg[jp * 2][0]     = t4[0];
                breg[jp * 2 + 1][0] = t4[1];
                breg[jp * 2][1]     = t4[2];
                breg[jp * 2 + 1][1] = t4[3];
            }
#pragma unroll
            for (int mi = 0; mi < 4; mi++)
#pragma unroll
                for (int j = 0; j < 4; j++)
                    mma16832f8(acc[mi][j], areg[mi], breg[j]);
        }

        __syncthreads();
        if (tid == 0 && k + NST < NCH) {
            mbar_expect(mb0 + st * 8, 2 * BLKB);
            bulk_cp(sBase + st * 2 * BLKB,        gA + (size_t)(k + NST) * BLKB, BLKB, mb0 + st * 8);
            bulk_cp(sBase + st * 2 * BLKB + BLKB, gB + (size_t)(k + NST) * BLKB, BLKB, mb0 + st * 8);
        }
    }

    // ---- epilogue: unscale + ext-bias + RoPE -> bf16 swizzled blocks -------
    const int g = lane >> 2, q = lane & 3;
#pragma unroll
    for (int mi = 0; mi < 4; mi++) {
#pragma unroll
        for (int h = 0; h < 2; h++) {
            int row = warpM * 64 + mi * 16 + h * 8 + g;
            int s = (m0 + row) & 511;
#pragma unroll
            for (int j = 0; j < 4; j++) {
                int c = warpN * 32 + j * 8 + 2 * q;
                float x = acc[mi][j][h * 2]     * WISCALE + bias_s[c];
                float y = acc[mi][j][h * 2 + 1] * WISCALE + bias_s[c + 1];
                int t = (c & 63) >> 1;
                float2 rc = g_rope[s * 32 + t];
                float rx = x * rc.x - y * rc.y;
                float ry = y * rc.x + x * rc.y;
                __nv_bfloat162 p = __floats2bfloat162_rn(rx, ry);
                int qk = c >> 6, col = c & 63;
                size_t blk = ((size_t)(bidx * ENT + e) * 2 + qk) * 4 + stile;
                size_t off = blk * BLKB + dswz(row, (col >> 3) << 4) + (col & 7) * 2;
                *(uint32_t*)(g_qk_blk + off) = *(uint32_t*)&p;
            }
        }
    }
}

// ---------------------------------------------------------------------------
// Kernel 3: logits (bf16, validated R8: 91us, near write floor — unchanged)
// ---------------------------------------------------------------------------
#define DSMEM_LOG (2 * BLKB)

__global__ __launch_bounds__(256) void logits_kernel(const float* __restrict__ mask,
                                                     float* __restrict__ out)
{
    extern __shared__ char lsm[];
    const uint32_t sQ = smem_u32(lsm);
    const uint32_t sK = sQ + BLKB;
    __shared__ uint64_t mbv;
    const uint32_t mb = smem_u32(&mbv);

    const int e = blockIdx.y;
    const int b = blockIdx.z;
    const int mt = blockIdx.x >> 2, nt = blockIdx.x & 3;
    const int m0 = mt * 128, n0 = nt * 128;
    const int tid = threadIdx.x;

    const size_t rowbase = ((size_t)(b * ENT + e)) * SS;

    if (mt > nt) {
        int cg = (tid & 31) * 4;
        float4 v;
        {
            float p0 = mask[b * SS + n0 + cg];
            float p1 = mask[b * SS + n0 + cg + 1];
            float p2 = mask[b * SS + n0 + cg + 2];
            float p3 = mask[b * SS + n0 + cg + 3];
            v = make_float4(((p0 - 1.0f) * BIGF - BIGF) * 0.125f,
                            ((p1 - 1.0f) * BIGF - BIGF) * 0.125f,
                            ((p2 - 1.0f) * BIGF - BIGF) * 0.125f,
                            ((p3 - 1.0f) * BIGF - BIGF) * 0.125f);
        }
        for (int r = tid >> 5; r < 128; r += 8)
            __stcs((float4*)(out + (rowbase + m0 + r) * SS + n0 + cg), v);
        return;
    }

    if (tid == 0) mbar_init(mb, 1);
    __syncthreads();
    if (tid == 0) {
        size_t base = (size_t)(b * ENT + e) * 2;
        mbar_expect(mb, 2 * BLKB);
        bulk_cp(sQ, g_qk_blk + (base * 4 + mt) * BLKB,       BLKB, mb);
        bulk_cp(sK, g_qk_blk + ((base + 1) * 4 + nt) * BLKB, BLKB, mb);
    }

    const int lane = tid & 31;
    const int wid  = tid >> 5;
    const int warpM = wid >> 2;
    const int warpN = wid & 3;

    mbar_wait(mb, 0u);

    float acc[4][4][4];
#pragma unroll
    for (int i = 0; i < 4; i++)
#pragma unroll
        for (int j = 0; j < 4; j++)
#pragma unroll
            for (int r = 0; r < 4; r++) acc[i][j][r] = 0.0f;

#pragma unroll
    for (int kstep = 0; kstep < 4; kstep++) {
        const int colb = kstep * 32 + (lane >> 4) * 16;
        uint32_t areg[4][4], breg[4][2];
#pragma unroll
        for (int mi = 0; mi < 4; mi++)
            ldsm4(areg[mi], sQ + dswz(warpM * 64 + mi * 16 + (lane & 15), colb));
#pragma unroll
        for (int jp = 0; jp < 2; jp++) {
            uint32_t t4[4];
            ldsm4(t4, sK + dswz(warpN * 32 + jp * 16 + (lane & 15), colb));
            breg[jp * 2][0]     = t4[0];
            breg[jp * 2 + 1][0] = t4[1];
            breg[jp * 2][1]     = t4[2];
            breg[jp * 2 + 1][1] = t4[3];
        }
#pragma unroll
        for (int mi = 0; mi < 4; mi++)
#pragma unroll
            for (int j = 0; j < 4; j++)
                mma16816(acc[mi][j], areg[mi], breg[j]);
    }

    const int g = lane >> 2, q = lane & 3;
    const int nbase = n0 + warpN * 32;
    float p0[4], p1[4];
#pragma unroll
    for (int j = 0; j < 4; j++) {
        int c = nbase + j * 8 + 2 * q;
        p0[j] = mask[b * SS + c];
        p1[j] = mask[b * SS + c + 1];
    }

#pragma unroll
    for (int mi = 0; mi < 4; mi++) {
#pragma unroll
        for (int h = 0; h < 2; h++) {
            int m = m0 + warpM * 64 + mi * 16 + h * 8 + g;
            size_t orow = (rowbase + m) * SS;
#pragma unroll
            for (int j = 0; j < 4; j++) {
                int c = nbase + j * 8 + 2 * q;
                float x = acc[mi][j][h * 2];
                float y = acc[mi][j][h * 2 + 1];
                x = x * p0[j] - (1.0f - p0[j]) * BIGF;
                y = y * p1[j] - (1.0f - p1[j]) * BIGF;
                if (m > c)     x -= BIGF;
                if (m > c + 1) y -= BIGF;
                __stcs((float2*)(out + orow + c), make_float2(x * 0.125f, y * 0.125f));
            }
        }
    }
}

// ---------------------------------------------------------------------------
extern "C" void kernel_launch(void* const* d_in, const int* in_sizes, int n_in,
                              void* d_out, int out_size)
{
    const float* lhs    = (const float*)d_in[0];
    const float* cls    = (const float*)d_in[1];
    const float* h0     = (const float*)d_in[2];
    const float* mask   = (const float*)d_in[3];
    const float* w_ih_f = (const float*)d_in[4];
    const float* w_hh_f = (const float*)d_in[5];
    const float* b_ih_f = (const float*)d_in[6];
    const float* b_hh_f = (const float*)d_in[7];
    const float* w_ih_b = (const float*)d_in[8];
    const float* w_hh_b = (const float*)d_in[9];
    const float* b_ih_b = (const float*)d_in[10];
    const float* b_hh_b = (const float*)d_in[11];
    const float* dw     = (const float*)d_in[12];
    const float* db     = (const float*)d_in[13];
    float* out = (float*)d_out;

    cudaFuncSetAttribute(dense_mma_kernel, cudaFuncAttributeMaxDynamicSharedMemorySize, DSMEM_DENSE);
    cudaFuncSetAttribute(logits_kernel,    cudaFuncAttributeMaxDynamicSharedMemorySize, DSMEM_LOG);

    prep_kernel<<<PREPB, 256>>>(dw, lhs, cls, h0, w_ih_f, w_hh_f, b_ih_f, b_hh_f,
                                w_ih_b, w_hh_b, b_ih_b, b_hh_b);
    clsw_kernel<<<NOUT / 64, 256>>>(dw, db);

    dense_mma_kernel<<<dim3(ENT, MDIM / 128), 256, DSMEM_DENSE>>>();

    logits_kernel<<<dim3(16, ENT, BB), 256, DSMEM_LOG>>>(mask, out);
}

// round 10
// speedup vs baseline: 2.1673x; 1.2932x over previous
#include <cuda_runtime.h>
#include <cuda_bf16.h>
#include <cuda_fp8.h>
#include <math.h>
#include <stdint.h>

#define ENT   52
#define INNER 64
#define BB    8
#define SS    512
#define HH    768
#define NOUT  6656    /* ENT*2*INNER */
#define KDIM  1536
#define MDIM  4096    /* BB*SS */
#define BIGF  1000000000000.0f
#define BLKB  16384   /* one 16KB swizzled block */
#define WSCALE 32.0f
#define WISCALE (1.0f / 32.0f)

// ---------------- scratch (device globals; no allocations allowed) ----------
__device__ float g_cls_emb[BB * HH];
__device__ float g_clsw[BB * NOUT];
__device__ __align__(16) uint8_t g_hidden_blk[(size_t)32 * 6 * BLKB];         // 3.1 MB
__device__ __align__(16) uint8_t g_wbf_blk[(size_t)ENT * 6 * BLKB];           // 5.1 MB
__device__ __align__(16) uint8_t g_qk_blk[(size_t)BB * ENT * 2 * 4 * BLKB];   // 54.5 MB
__device__ float2 g_rope[SS * 32];

// ---------------- PTX helpers ----------------------------------------------
__device__ __forceinline__ uint32_t smem_u32(const void* p) {
    uint32_t a;
    asm("{ .reg .u64 t; cvta.to.shared.u64 t, %1; cvt.u32.u64 %0, t; }" : "=r"(a) : "l"(p));
    return a;
}
__device__ __forceinline__ void mbar_init(uint32_t a, uint32_t n) {
    asm volatile("mbarrier.init.shared.b64 [%0], %1;" :: "r"(a), "r"(n) : "memory");
}
__device__ __forceinline__ void mbar_expect(uint32_t a, uint32_t tx) {
    asm volatile("mbarrier.arrive.expect_tx.shared.b64 _, [%0], %1;" :: "r"(a), "r"(tx) : "memory");
}
__device__ __forceinline__ void mbar_wait(uint32_t a, uint32_t ph) {
    asm volatile("{\n\t.reg .pred P;\n\t"
                 "LW_%=:\n\t"
                 "mbarrier.try_wait.parity.shared.b64 P, [%0], %1;\n\t"
                 "@!P bra LW_%=;\n\t}"
                 :: "r"(a), "r"(ph) : "memory");
}
__device__ __forceinline__ void bulk_cp(uint32_t dst, const void* src, uint32_t bytes,
                                        uint32_t mbar) {
    asm volatile("cp.async.bulk.shared::cta.global.mbarrier::complete_tx::bytes "
                 "[%0], [%1], %2, [%3];"
                 :: "r"(dst), "l"(src), "r"(bytes), "r"(mbar) : "memory");
}
__device__ __forceinline__ void ldsm4(uint32_t* r, uint32_t addr) {
    asm volatile("ldmatrix.sync.aligned.m8n8.x4.shared.b16 {%0,%1,%2,%3}, [%4];"
                 : "=r"(r[0]), "=r"(r[1]), "=r"(r[2]), "=r"(r[3]) : "r"(addr));
}
__device__ __forceinline__ void mma16816(float* c, const uint32_t* a, const uint32_t* b) {
    asm volatile(
        "mma.sync.aligned.m16n8k16.row.col.f32.bf16.bf16.f32 "
        "{%0,%1,%2,%3}, {%4,%5,%6,%7}, {%8,%9}, {%0,%1,%2,%3};"
        : "+f"(c[0]), "+f"(c[1]), "+f"(c[2]), "+f"(c[3])
        : "r"(a[0]), "r"(a[1]), "r"(a[2]), "r"(a[3]), "r"(b[0]), "r"(b[1]));
}
__device__ __forceinline__ void mma16832f8(float* c, const uint32_t* a, const uint32_t* b) {
    asm volatile(
        "mma.sync.aligned.m16n8k32.row.col.f32.e4m3.e4m3.f32 "
        "{%0,%1,%2,%3}, {%4,%5,%6,%7}, {%8,%9}, {%0,%1,%2,%3};"
        : "+f"(c[0]), "+f"(c[1]), "+f"(c[2]), "+f"(c[3])
        : "r"(a[0]), "r"(a[1]), "r"(a[2]), "r"(a[3]), "r"(b[0]), "r"(b[1]));
}
__device__ __forceinline__ uint32_t dswz(int row, int colb) {
    return (uint32_t)(row * 128 + (colb ^ ((row & 7) << 4)));
}
__device__ __forceinline__ uint32_t fp8x4(float a, float b, float c, float d) {
    __nv_fp8x2_storage_t lo = __nv_cvt_float2_to_fp8x2(make_float2(a, b),
                                                       __NV_SATFINITE, __NV_E4M3);
    __nv_fp8x2_storage_t hi = __nv_cvt_float2_to_fp8x2(make_float2(c, d),
                                                       __NV_SATFINITE, __NV_E4M3);
    return (uint32_t)lo | ((uint32_t)hi << 16);
}

// ---------------------------------------------------------------------------
// Kernel 1 (fused prep) — block ranges, in scheduling order:
//   [0,96)          GRU cells (4-way k-split, latency-critical -> first)
//   [96,160)        rope table
//   [160,2656)      causal-skip logits tiles (pure streaming writes)
//   [2656,7648)     W1 fp32 -> fp8 blocks
//   [7648,10720)    lhs fp32 -> fp8 blocks
// ---------------------------------------------------------------------------
#define GRUB2 96
#define ROPEB 64
#define SKIPB 2496
#define CONVB (NOUT * HH / 4 / 256)    /* 4992 */
#define BHB   (MDIM * HH / 4 / 256)    /* 3072 */
#define PREPB (GRUB2 + ROPEB + SKIPB + CONVB + BHB)

__global__ __launch_bounds__(256) void prep_kernel(
    const float* __restrict__ dw, const float* __restrict__ lhs,
    const float* __restrict__ cls, const float* __restrict__ h0,
    const float* __restrict__ w_ih_f, const float* __restrict__ w_hh_f,
    const float* __restrict__ b_ih_f, const float* __restrict__ b_hh_f,
    const float* __restrict__ w_ih_b, const float* __restrict__ w_hh_b,
    const float* __restrict__ b_ih_b, const float* __restrict__ b_hh_b,
    const float* __restrict__ mask, float* __restrict__ out)
{
    const int bid = blockIdx.x;
    const int tid = threadIdx.x;

    if (bid < GRUB2) {
        // ---- GRU: 96 blocks = 48 unit-chunks x 2 dirs.
        //      256 thr = 8 units x 8 batches x 4 ksplits, shfl reduce.
        const int dir = bid / 48;
        const int u   = (bid % 48) * 8 + (tid >> 5);
        const int rest = tid & 31;
        const int b  = rest >> 2;
        const int ks = rest & 3;

        const float* w_ih = dir ? w_ih_b : w_ih_f;
        const float* w_hh = dir ? w_hh_b : w_hh_f;
        const float* b_ih = dir ? b_ih_b : b_ih_f;
        const float* b_hh = dir ? b_hh_b : b_hh_f;

        const float* xv = cls + b * HH;
        const float* hv = h0 + ((size_t)dir * BB + b) * 384;

        float gi[3], gh[3];
#pragma unroll
        for (int g = 0; g < 3; g++) {
            const float* w = w_ih + (size_t)(g * 384 + u) * HH + ks * 192;
            const float* x = xv + ks * 192;
            float acc = 0.0f;
#pragma unroll 8
            for (int k = 0; k < 192; k += 4) {
                float4 wq = *(const float4*)(w + k);
                float4 xq = *(const float4*)(x + k);
                acc += wq.x * xq.x + wq.y * xq.y + wq.z * xq.z + wq.w * xq.w;
            }
            gi[g] = acc;
            const float* w2 = w_hh + (size_t)(g * 384 + u) * 384 + ks * 96;
            const float* h2 = hv + ks * 96;
            float acc2 = 0.0f;
#pragma unroll 8
            for (int k = 0; k < 96; k += 4) {
                float4 wq = *(const float4*)(w2 + k);
                float4 hq = *(const float4*)(h2 + k);
                acc2 += wq.x * hq.x + wq.y * hq.y + wq.z * hq.z + wq.w * hq.w;
            }
            gh[g] = acc2;
        }
#pragma unroll
        for (int g = 0; g < 3; g++) {
            gi[g] += __shfl_xor_sync(0xFFFFFFFF, gi[g], 1);
            gi[g] += __shfl_xor_sync(0xFFFFFFFF, gi[g], 2);
            gh[g] += __shfl_xor_sync(0xFFFFFFFF, gh[g], 1);
            gh[g] += __shfl_xor_sync(0xFFFFFFFF, gh[g], 2);
        }
        if (ks == 0) {
            float i0 = gi[0] + b_ih[u],        h0v = gh[0] + b_hh[u];
            float i1 = gi[1] + b_ih[384 + u],  h1v = gh[1] + b_hh[384 + u];
            float i2 = gi[2] + b_ih[768 + u],  h2v = gh[2] + b_hh[768 + u];
            float r = 1.0f / (1.0f + expf(-(i0 + h0v)));
            float z = 1.0f / (1.0f + expf(-(i1 + h1v)));
            float n = tanhf(i2 + r * h2v);
            float hp = hv[u];
            g_cls_emb[b * HH + dir * 384 + u] = (1.0f - z) * n + z * hp;
        }
        return;
    }
    if (bid < GRUB2 + ROPEB) {
        int idx = (bid - GRUB2) * 256 + tid;
        int s = idx >> 5, t = idx & 31;
        float invf = powf(10000.0f, -2.0f * (float)t / 64.0f);
        float sn, cs;
        sincosf((float)s * invf, &sn, &cs);
        g_rope[idx] = make_float2(cs, sn);
        return;
    }
    if (bid < GRUB2 + ROPEB + SKIPB) {
        // ---- causal-skip tiles: mt > nt, pure masked-constant writes ----
        const int MTs[6] = {1, 2, 2, 3, 3, 3};
        const int NTs[6] = {0, 0, 1, 0, 1, 2};
        int idx = bid - (GRUB2 + ROPEB);
        int ti = idx % 6;
        int be = idx / 6;
        int b = be / ENT, e = be % ENT;
        int m0 = MTs[ti] * 128, n0 = NTs[ti] * 128;
        size_t rowbase = ((size_t)(b * ENT + e)) * SS;
        int cg = (tid & 31) * 4;
        float p0 = mask[b * SS + n0 + cg];
        float p1 = mask[b * SS + n0 + cg + 1];
        float p2 = mask[b * SS + n0 + cg + 2];
        float p3 = mask[b * SS + n0 + cg + 3];
        float4 v = make_float4(((p0 - 1.0f) * BIGF - BIGF) * 0.125f,
                               ((p1 - 1.0f) * BIGF - BIGF) * 0.125f,
                               ((p2 - 1.0f) * BIGF - BIGF) * 0.125f,
                               ((p3 - 1.0f) * BIGF - BIGF) * 0.125f);
        for (int r = tid >> 5; r < 128; r += 8)
            __stcs((float4*)(out + (rowbase + m0 + r) * SS + n0 + cg), v);
        return;
    }
    if (bid < GRUB2 + ROPEB + SKIPB + CONVB) {
        // ---- W1 fp32 -> fp8 (x32), swizzled block layout ----
        int i = (bid - (GRUB2 + ROPEB + SKIPB)) * 256 + tid;
        int n  = i / 192;
        int kq = (i % 192) * 4;
        float4 v = *(const float4*)(dw + (size_t)n * KDIM + kq);
        uint32_t w = fp8x4(v.x * WSCALE, v.y * WSCALE, v.z * WSCALE, v.w * WSCALE);
        int e = n >> 7, row = n & 127, ch = kq >> 7, kc = kq & 127;
        size_t off = (size_t)(e * 6 + ch) * BLKB + dswz(row, kc & 0x70) + (kc & 15);
        *(uint32_t*)(g_wbf_blk + off) = w;
        return;
    }
    {
        // ---- lhs fp32 -> fp8, swizzled block layout ----
        size_t gid = (size_t)(bid - (GRUB2 + ROPEB + SKIPB + CONVB)) * 256 + tid;
        size_t i = gid * 4;
        float4 v = *(const float4*)(lhs + i);
        uint32_t w = fp8x4(v.x, v.y, v.z, v.w);
        int m = (int)(i / HH), k = (int)(i % HH);
        int mt = m >> 7, row = m & 127, ch = k >> 7, kc = k & 127;
        size_t off = (size_t)(mt * 6 + ch) * BLKB + dswz(row, kc & 0x70) + (kc & 15);
        *(uint32_t*)(g_hidden_blk + off) = w;
    }
}

// ---------------------------------------------------------------------------
// Kernel 1b: extended bias, 4-way K-split. grid 104, 256 thr = 64 n x 4 kseg.
// ---------------------------------------------------------------------------
__global__ __launch_bounds__(256) void clsw_kernel(const float* __restrict__ dw,
                                                   const float* __restrict__ db)
{
    __shared__ float cl[BB][HH + 4];
    __shared__ float red[4][64][BB];
    for (int i = threadIdx.x; i < BB * HH; i += 256)
        cl[i / HH][i % HH] = g_cls_emb[i];
    __syncthreads();

    const int nl = threadIdx.x & 63;
    const int ks = threadIdx.x >> 6;
    const int n  = blockIdx.x * 64 + nl;
    const int k0 = ks * 192;

    const float* w = dw + (size_t)n * KDIM + HH + k0;
    float acc[BB];
#pragma unroll
    for (int b = 0; b < BB; b++) acc[b] = 0.0f;
#pragma unroll 4
    for (int k = 0; k < 192; k += 4) {
        float4 wv = *(const float4*)(w + k);
#pragma unroll
        for (int b = 0; b < BB; b++)
            acc[b] += wv.x * cl[b][k0 + k] + wv.y * cl[b][k0 + k + 1]
                    + wv.z * cl[b][k0 + k + 2] + wv.w * cl[b][k0 + k + 3];
    }
#pragma unroll
    for (int b = 0; b < BB; b++) red[ks][nl][b] = acc[b];
    __syncthreads();
    if (ks == 0) {
        float bias = db[n];
#pragma unroll
        for (int b = 0; b < BB; b++)
            g_clsw[b * NOUT + n] = red[0][nl][b] + red[1][nl][b] + red[2][nl][b]
                                 + red[3][nl][b] + bias;
    }
}

// ---------------------------------------------------------------------------
// Kernel 2: dense GEMM in fp8 e4m3 (m16n8k32), bulk-copy pipeline.
// (validated R9 — unchanged)
// ---------------------------------------------------------------------------
#define NST   3
#define DSMEM_DENSE (NST * 2 * BLKB)   /* 98304 */

__global__ __launch_bounds__(256, 2) void dense_mma_kernel()
{
    extern __shared__ char dsm[];
    const uint32_t sBase = smem_u32(dsm);
    __shared__ uint64_t mbv[NST];
    __shared__ float bias_s[128];
    const uint32_t mb0 = smem_u32(mbv);

    const int e  = blockIdx.x;
    const int mt = blockIdx.y;
    const int m0 = mt * 128;
    const int n0 = e * 128;
    const int bidx = mt >> 2;
    const int stile = mt & 3;
    const int tid = threadIdx.x;
    const int lane = tid & 31;
    const int wid  = tid >> 5;
    const int warpM = wid >> 2;
    const int warpN = wid & 3;

    if (tid < 128) bias_s[tid] = g_clsw[bidx * NOUT + n0 + tid];
    if (tid == 0) {
#pragma unroll
        for (int s = 0; s < NST; s++) mbar_init(mb0 + s * 8, 1);
    }
    __syncthreads();

    const uint8_t* gA = g_hidden_blk + (size_t)mt * 6 * BLKB;
    const uint8_t* gB = g_wbf_blk    + (size_t)e  * 6 * BLKB;

    if (tid == 0) {
#pragma unroll
        for (int s = 0; s < NST; s++) {
            mbar_expect(mb0 + s * 8, 2 * BLKB);
            bulk_cp(sBase + s * 2 * BLKB,        gA + (size_t)s * BLKB, BLKB, mb0 + s * 8);
            bulk_cp(sBase + s * 2 * BLKB + BLKB, gB + (size_t)s * BLKB, BLKB, mb0 + s * 8);
        }
    }

    float acc[4][4][4];
#pragma unroll
    for (int i = 0; i < 4; i++)
#pragma unroll
        for (int j = 0; j < 4; j++)
#pragma unroll
            for (int r = 0; r < 4; r++) acc[i][j][r] = 0.0f;

    const int NCH = 6;
    for (int k = 0; k < NCH; k++) {
        const int st = k % NST;
        mbar_wait(mb0 + st * 8, (uint32_t)((k / NST) & 1));

        const uint32_t aS = sBase + st * 2 * BLKB;
        const uint32_t bS = aS + BLKB;
#pragma unroll
        for (int kstep = 0; kstep < 4; kstep++) {
            const int colb = kstep * 32 + (lane >> 4) * 16;
            uint32_t areg[4][4], breg[4][2];
#pragma unroll
            for (int mi = 0; mi < 4; mi++)
                ldsm4(areg[mi], aS + dswz(warpM * 64 + mi * 16 + (lane & 15), colb));
#pragma unroll
            for (int jp = 0; jp < 2; jp++) {
                uint32_t t4[4];
                ldsm4(t4, bS + dswz(warpN * 32 + jp * 16 + (lane & 15), colb));
                breg[jp * 2][0]     = t4[0];
                breg[jp * 2 + 1][0] = t4[1];
                breg[jp * 2][1]     = t4[2];
                breg[jp * 2 + 1][1] = t4[3];
            }
#pragma unroll
            for (int mi = 0; mi < 4; mi++)
#pragma unroll
                for (int j = 0; j < 4; j++)
                    mma16832f8(acc[mi][j], areg[mi], breg[j]);
        }

        __syncthreads();
        if (tid == 0 && k + NST < NCH) {
            mbar_expect(mb0 + st * 8, 2 * BLKB);
            bulk_cp(sBase + st * 2 * BLKB,        gA + (size_t)(k + NST) * BLKB, BLKB, mb0 + st * 8);
            bulk_cp(sBase + st * 2 * BLKB + BLKB, gB + (size_t)(k + NST) * BLKB, BLKB, mb0 + st * 8);
        }
    }

    // ---- epilogue: unscale + ext-bias + RoPE -> bf16 swizzled blocks -------
    const int g = lane >> 2, q = lane & 3;
#pragma unroll
    for (int mi = 0; mi < 4; mi++) {
#pragma unroll
        for (int h = 0; h < 2; h++) {
            int row = warpM * 64 + mi * 16 + h * 8 + g;
            int s = (m0 + row) & 511;
#pragma unroll
            for (int j = 0; j < 4; j++) {
                int c = warpN * 32 + j * 8 + 2 * q;
                float x = acc[mi][j][h * 2]     * WISCALE + bias_s[c];
                float y = acc[mi][j][h * 2 + 1] * WISCALE + bias_s[c + 1];
                int t = (c & 63) >> 1;
                float2 rc = g_rope[s * 32 + t];
                float rx = x * rc.x - y * rc.y;
                float ry = y * rc.x + x * rc.y;
                __nv_bfloat162 p = __floats2bfloat162_rn(rx, ry);
                int qk = c >> 6, col = c & 63;
                size_t blk = ((size_t)(bidx * ENT + e) * 2 + qk) * 4 + stile;
                size_t off = blk * BLKB + dswz(row, (col >> 3) << 4) + (col & 7) * 2;
                *(uint32_t*)(g_qk_blk + off) = *(uint32_t*)&p;
            }
        }
    }
}

// ---------------------------------------------------------------------------
// Kernel 3: logits — compute tiles ONLY (10 upper-tri tiles per (b,e));
// skip tiles moved into prep. grid (10, 52, 8), 256 threads.
// ---------------------------------------------------------------------------
#define DSMEM_LOG (2 * BLKB)

__global__ __launch_bounds__(256) void logits_kernel(const float* __restrict__ mask,
                                                     float* __restrict__ out)
{
    extern __shared__ char lsm[];
    const uint32_t sQ = smem_u32(lsm);
    const uint32_t sK = sQ + BLKB;
    __shared__ uint64_t mbv;
    const uint32_t mb = smem_u32(&mbv);

    const int MTs[10] = {0, 0, 0, 0, 1, 1, 1, 2, 2, 3};
    const int NTs[10] = {0, 1, 2, 3, 1, 2, 3, 2, 3, 3};

    const int e = blockIdx.y;
    const int b = blockIdx.z;
    const int mt = MTs[blockIdx.x], nt = NTs[blockIdx.x];
    const int m0 = mt * 128, n0 = nt * 128;
    const int tid = threadIdx.x;

    const size_t rowbase = ((size_t)(b * ENT + e)) * SS;

    if (tid == 0) mbar_init(mb, 1);
    __syncthreads();
    if (tid == 0) {
        size_t base = (size_t)(b * ENT + e) * 2;
        mbar_expect(mb, 2 * BLKB);
        bulk_cp(sQ, g_qk_blk + (base * 4 + mt) * BLKB,       BLKB, mb);
        bulk_cp(sK, g_qk_blk + ((base + 1) * 4 + nt) * BLKB, BLKB, mb);
    }

    const int lane = tid & 31;
    const int wid  = tid >> 5;
    const int warpM = wid >> 2;
    const int warpN = wid & 3;

    mbar_wait(mb, 0u);

    float acc[4][4][4];
#pragma unroll
    for (int i = 0; i < 4; i++)
#pragma unroll
        for (int j = 0; j < 4; j++)
#pragma unroll
            for (int r = 0; r < 4; r++) acc[i][j][r] = 0.0f;

#pragma unroll
    for (int kstep = 0; kstep < 4; kstep++) {
        const int colb = kstep * 32 + (lane >> 4) * 16;
        uint32_t areg[4][4], breg[4][2];
#pragma unroll
        for (int mi = 0; mi < 4; mi++)
            ldsm4(areg[mi], sQ + dswz(warpM * 64 + mi * 16 + (lane & 15), colb));
#pragma unroll
        for (int jp = 0; jp < 2; jp++) {
            uint32_t t4[4];
            ldsm4(t4, sK + dswz(warpN * 32 + jp * 16 + (lane & 15), colb));
            breg[jp * 2][0]     = t4[0];
            breg[jp * 2 + 1][0] = t4[1];
            breg[jp * 2][1]     = t4[2];
            breg[jp * 2 + 1][1] = t4[3];
        }
#pragma unroll
        for (int mi = 0; mi < 4; mi++)
#pragma unroll
            for (int j = 0; j < 4; j++)
                mma16816(acc[mi][j], areg[mi], breg[j]);
    }

    const int g = lane >> 2, q = lane & 3;
    const int nbase = n0 + warpN * 32;
    float p0[4], p1[4];
#pragma unroll
    for (int j = 0; j < 4; j++) {
        int c = nbase + j * 8 + 2 * q;
        p0[j] = mask[b * SS + c];
        p1[j] = mask[b * SS + c + 1];
    }

#pragma unroll
    for (int mi = 0; mi < 4; mi++) {
#pragma unroll
        for (int h = 0; h < 2; h++) {
            int m = m0 + warpM * 64 + mi * 16 + h * 8 + g;
            size_t orow = (rowbase + m) * SS;
#pragma unroll
            for (int j = 0; j < 4; j++) {
                int c = nbase + j * 8 + 2 * q;
                float x = acc[mi][j][h * 2];
                float y = acc[mi][j][h * 2 + 1];
                x = x * p0[j] - (1.0f - p0[j]) * BIGF;
                y = y * p1[j] - (1.0f - p1[j]) * BIGF;
                if (m > c)     x -= BIGF;
                if (m > c + 1) y -= BIGF;
                __stcs((float2*)(out + orow + c), make_float2(x * 0.125f, y * 0.125f));
            }
        }
    }
}

// ---------------------------------------------------------------------------
extern "C" void kernel_launch(void* const* d_in, const int* in_sizes, int n_in,
                              void* d_out, int out_size)
{
    const float* lhs    = (const float*)d_in[0];
    const float* cls    = (const float*)d_in[1];
    const float* h0     = (const float*)d_in[2];
    const float* mask   = (const float*)d_in[3];
    const float* w_ih_f = (const float*)d_in[4];
    const float* w_hh_f = (const float*)d_in[5];
    const float* b_ih_f = (const float*)d_in[6];
    const float* b_hh_f = (const float*)d_in[7];
    const float* w_ih_b = (const float*)d_in[8];
    const float* w_hh_b = (const float*)d_in[9];
    const float* b_ih_b = (const float*)d_in[10];
    const float* b_hh_b = (const float*)d_in[11];
    const float* dw     = (const float*)d_in[12];
    const float* db     = (const float*)d_in[13];
    float* out = (float*)d_out;

    cudaFuncSetAttribute(dense_mma_kernel, cudaFuncAttributeMaxDynamicSharedMemorySize, DSMEM_DENSE);
    cudaFuncSetAttribute(logits_kernel,    cudaFuncAttributeMaxDynamicSharedMemorySize, DSMEM_LOG);

    prep_kernel<<<PREPB, 256>>>(dw, lhs, cls, h0, w_ih_f, w_hh_f, b_ih_f, b_hh_f,
                                w_ih_b, w_hh_b, b_ih_b, b_hh_b, mask, out);
    clsw_kernel<<<NOUT / 64, 256>>>(dw, db);

    dense_mma_kernel<<<dim3(ENT, MDIM / 128), 256, DSMEM_DENSE>>>();

    logits_kernel<<<dim3(10, ENT, BB), 256, DSMEM_LOG>>>(mask, out);
}

// round 11
// speedup vs baseline: 2.2344x; 1.0309x over previous
#include <cuda_runtime.h>
#include <cuda_bf16.h>
#include <cuda_fp8.h>
#include <math.h>
#include <stdint.h>

#define ENT   52
#define INNER 64
#define BB    8
#define SS    512
#define HH    768
#define NOUT  6656    /* ENT*2*INNER */
#define KDIM  1536
#define MDIM  4096    /* BB*SS */
#define BIGF  1000000000000.0f
#define BLKB  16384   /* one 16KB swizzled block */
#define WSCALE 32.0f
#define WISCALE (1.0f / 32.0f)

// ---------------- scratch (device globals; no allocations allowed) ----------
__device__ float g_cls_emb[BB * HH];
__device__ float g_clsw[BB * NOUT];
__device__ __align__(16) uint8_t g_hidden_blk[(size_t)32 * 6 * BLKB];         // 3.1 MB
__device__ __align__(16) uint8_t g_wbf_blk[(size_t)ENT * 6 * BLKB];           // 5.1 MB
__device__ float2 g_rope[SS * 32];

// ---------------- PTX helpers ----------------------------------------------
__device__ __forceinline__ uint32_t smem_u32(const void* p) {
    uint32_t a;
    asm("{ .reg .u64 t; cvta.to.shared.u64 t, %1; cvt.u32.u64 %0, t; }" : "=r"(a) : "l"(p));
    return a;
}
__device__ __forceinline__ void mbar_init(uint32_t a, uint32_t n) {
    asm volatile("mbarrier.init.shared.b64 [%0], %1;" :: "r"(a), "r"(n) : "memory");
}
__device__ __forceinline__ void mbar_expect(uint32_t a, uint32_t tx) {
    asm volatile("mbarrier.arrive.expect_tx.shared.b64 _, [%0], %1;" :: "r"(a), "r"(tx) : "memory");
}
__device__ __forceinline__ void mbar_wait(uint32_t a, uint32_t ph) {
    asm volatile("{\n\t.reg .pred P;\n\t"
                 "LW_%=:\n\t"
                 "mbarrier.try_wait.parity.shared.b64 P, [%0], %1;\n\t"
                 "@!P bra LW_%=;\n\t}"
                 :: "r"(a), "r"(ph) : "memory");
}
__device__ __forceinline__ void bulk_cp(uint32_t dst, const void* src, uint32_t bytes,
                                        uint32_t mbar) {
    asm volatile("cp.async.bulk.shared::cta.global.mbarrier::complete_tx::bytes "
                 "[%0], [%1], %2, [%3];"
                 :: "r"(dst), "l"(src), "r"(bytes), "r"(mbar) : "memory");
}
__device__ __forceinline__ void ldsm4(uint32_t* r, uint32_t addr) {
    asm volatile("ldmatrix.sync.aligned.m8n8.x4.shared.b16 {%0,%1,%2,%3}, [%4];"
                 : "=r"(r[0]), "=r"(r[1]), "=r"(r[2]), "=r"(r[3]) : "r"(addr));
}
__device__ __forceinline__ void mma16816(float* c, const uint32_t* a, const uint32_t* b) {
    asm volatile(
        "mma.sync.aligned.m16n8k16.row.col.f32.bf16.bf16.f32 "
        "{%0,%1,%2,%3}, {%4,%5,%6,%7}, {%8,%9}, {%0,%1,%2,%3};"
        : "+f"(c[0]), "+f"(c[1]), "+f"(c[2]), "+f"(c[3])
        : "r"(a[0]), "r"(a[1]), "r"(a[2]), "r"(a[3]), "r"(b[0]), "r"(b[1]));
}
__device__ __forceinline__ void mma16832f8(float* c, const uint32_t* a, const uint32_t* b) {
    asm volatile(
        "mma.sync.aligned.m16n8k32.row.col.f32.e4m3.e4m3.f32 "
        "{%0,%1,%2,%3}, {%4,%5,%6,%7}, {%8,%9}, {%0,%1,%2,%3};"
        : "+f"(c[0]), "+f"(c[1]), "+f"(c[2]), "+f"(c[3])
        : "r"(a[0]), "r"(a[1]), "r"(a[2]), "r"(a[3]), "r"(b[0]), "r"(b[1]));
}
__device__ __forceinline__ uint32_t dswz(int row, int colb) {
    return (uint32_t)(row * 128 + (colb ^ ((row & 7) << 4)));
}
__device__ __forceinline__ uint32_t fp8x4(float a, float b, float c, float d) {
    __nv_fp8x2_storage_t lo = __nv_cvt_float2_to_fp8x2(make_float2(a, b),
                                                       __NV_SATFINITE, __NV_E4M3);
    __nv_fp8x2_storage_t hi = __nv_cvt_float2_to_fp8x2(make_float2(c, d),
                                                       __NV_SATFINITE, __NV_E4M3);
    return (uint32_t)lo | ((uint32_t)hi << 16);
}

// ---------------------------------------------------------------------------
// Kernel 1 (fused prep) — block ranges, in scheduling order:
//   [0,96) GRU | [96,160) rope | [160,2656) causal-skip tiles |
//   [2656,7648) W1->fp8 | [7648,10720) lhs->fp8
// ---------------------------------------------------------------------------
#define GRUB2 96
#define ROPEB 64
#define SKIPB 2496
#define CONVB (NOUT * HH / 4 / 256)    /* 4992 */
#define BHB   (MDIM * HH / 4 / 256)    /* 3072 */
#define PREPB (GRUB2 + ROPEB + SKIPB + CONVB + BHB)

__global__ __launch_bounds__(256) void prep_kernel(
    const float* __restrict__ dw, const float* __restrict__ lhs,
    const float* __restrict__ cls, const float* __restrict__ h0,
    const float* __restrict__ w_ih_f, const float* __restrict__ w_hh_f,
    const float* __restrict__ b_ih_f, const float* __restrict__ b_hh_f,
    const float* __restrict__ w_ih_b, const float* __restrict__ w_hh_b,
    const float* __restrict__ b_ih_b, const float* __restrict__ b_hh_b,
    const float* __restrict__ mask, float* __restrict__ out)
{
    const int bid = blockIdx.x;
    const int tid = threadIdx.x;

    if (bid < GRUB2) {
        const int dir = bid / 48;
        const int u   = (bid % 48) * 8 + (tid >> 5);
        const int rest = tid & 31;
        const int b  = rest >> 2;
        const int ks = rest & 3;

        const float* w_ih = dir ? w_ih_b : w_ih_f;
        const float* w_hh = dir ? w_hh_b : w_hh_f;
        const float* b_ih = dir ? b_ih_b : b_ih_f;
        const float* b_hh = dir ? b_hh_b : b_hh_f;

        const float* xv = cls + b * HH;
        const float* hv = h0 + ((size_t)dir * BB + b) * 384;

        float gi[3], gh[3];
#pragma unroll
        for (int g = 0; g < 3; g++) {
            const float* w = w_ih + (size_t)(g * 384 + u) * HH + ks * 192;
            const float* x = xv + ks * 192;
            float acc = 0.0f;
#pragma unroll 8
            for (int k = 0; k < 192; k += 4) {
                float4 wq = *(const float4*)(w + k);
                float4 xq = *(const float4*)(x + k);
                acc += wq.x * xq.x + wq.y * xq.y + wq.z * xq.z + wq.w * xq.w;
            }
            gi[g] = acc;
            const float* w2 = w_hh + (size_t)(g * 384 + u) * 384 + ks * 96;
            const float* h2 = hv + ks * 96;
            float acc2 = 0.0f;
#pragma unroll 8
            for (int k = 0; k < 96; k += 4) {
                float4 wq = *(const float4*)(w2 + k);
                float4 hq = *(const float4*)(h2 + k);
                acc2 += wq.x * hq.x + wq.y * hq.y + wq.z * hq.z + wq.w * hq.w;
            }
            gh[g] = acc2;
        }
#pragma unroll
        for (int g = 0; g < 3; g++) {
            gi[g] += __shfl_xor_sync(0xFFFFFFFF, gi[g], 1);
            gi[g] += __shfl_xor_sync(0xFFFFFFFF, gi[g], 2);
            gh[g] += __shfl_xor_sync(0xFFFFFFFF, gh[g], 1);
            gh[g] += __shfl_xor_sync(0xFFFFFFFF, gh[g], 2);
        }
        if (ks == 0) {
            float i0 = gi[0] + b_ih[u],        h0v = gh[0] + b_hh[u];
            float i1 = gi[1] + b_ih[384 + u],  h1v = gh[1] + b_hh[384 + u];
            float i2 = gi[2] + b_ih[768 + u],  h2v = gh[2] + b_hh[768 + u];
            float r = 1.0f / (1.0f + expf(-(i0 + h0v)));
            float z = 1.0f / (1.0f + expf(-(i1 + h1v)));
            float n = tanhf(i2 + r * h2v);
            float hp = hv[u];
            g_cls_emb[b * HH + dir * 384 + u] = (1.0f - z) * n + z * hp;
        }
        return;
    }
    if (bid < GRUB2 + ROPEB) {
        int idx = (bid - GRUB2) * 256 + tid;
        int s = idx >> 5, t = idx & 31;
        float invf = powf(10000.0f, -2.0f * (float)t / 64.0f);
        float sn, cs;
        sincosf((float)s * invf, &sn, &cs);
        g_rope[idx] = make_float2(cs, sn);
        return;
    }
    if (bid < GRUB2 + ROPEB + SKIPB) {
        const int MTs[6] = {1, 2, 2, 3, 3, 3};
        const int NTs[6] = {0, 0, 1, 0, 1, 2};
        int idx = bid - (GRUB2 + ROPEB);
        int ti = idx % 6;
        int be = idx / 6;
        int b = be / ENT, e = be % ENT;
        int m0 = MTs[ti] * 128, n0 = NTs[ti] * 128;
        size_t rowbase = ((size_t)(b * ENT + e)) * SS;
        int cg = (tid & 31) * 4;
        float p0 = mask[b * SS + n0 + cg];
        float p1 = mask[b * SS + n0 + cg + 1];
        float p2 = mask[b * SS + n0 + cg + 2];
        float p3 = mask[b * SS + n0 + cg + 3];
        float4 v = make_float4(((p0 - 1.0f) * BIGF - BIGF) * 0.125f,
                               ((p1 - 1.0f) * BIGF - BIGF) * 0.125f,
                               ((p2 - 1.0f) * BIGF - BIGF) * 0.125f,
                               ((p3 - 1.0f) * BIGF - BIGF) * 0.125f);
        for (int r = tid >> 5; r < 128; r += 8)
            __stcs((float4*)(out + (rowbase + m0 + r) * SS + n0 + cg), v);
        return;
    }
    if (bid < GRUB2 + ROPEB + SKIPB + CONVB) {
        int i = (bid - (GRUB2 + ROPEB + SKIPB)) * 256 + tid;
        int n  = i / 192;
        int kq = (i % 192) * 4;
        float4 v = *(const float4*)(dw + (size_t)n * KDIM + kq);
        uint32_t w = fp8x4(v.x * WSCALE, v.y * WSCALE, v.z * WSCALE, v.w * WSCALE);
        int e = n >> 7, row = n & 127, ch = kq >> 7, kc = kq & 127;
        size_t off = (size_t)(e * 6 + ch) * BLKB + dswz(row, kc & 0x70) + (kc & 15);
        *(uint32_t*)(g_wbf_blk + off) = w;
        return;
    }
    {
        size_t gid = (size_t)(bid - (GRUB2 + ROPEB + SKIPB + CONVB)) * 256 + tid;
        size_t i = gid * 4;
        float4 v = *(const float4*)(lhs + i);
        uint32_t w = fp8x4(v.x, v.y, v.z, v.w);
        int m = (int)(i / HH), k = (int)(i % HH);
        int mt = m >> 7, row = m & 127, ch = k >> 7, kc = k & 127;
        size_t off = (size_t)(mt * 6 + ch) * BLKB + dswz(row, kc & 0x70) + (kc & 15);
        *(uint32_t*)(g_hidden_blk + off) = w;
    }
}

// ---------------------------------------------------------------------------
// Kernel 1b: extended bias, 4-way K-split. (validated — unchanged)
// ---------------------------------------------------------------------------
__global__ __launch_bounds__(256) void clsw_kernel(const float* __restrict__ dw,
                                                   const float* __restrict__ db)
{
    __shared__ float cl[BB][HH + 4];
    __shared__ float red[4][64][BB];
    for (int i = threadIdx.x; i < BB * HH; i += 256)
        cl[i / HH][i % HH] = g_cls_emb[i];
    __syncthreads();

    const int nl = threadIdx.x & 63;
    const int ks = threadIdx.x >> 6;
    const int n  = blockIdx.x * 64 + nl;
    const int k0 = ks * 192;

    const float* w = dw + (size_t)n * KDIM + HH + k0;
    float acc[BB];
#pragma unroll
    for (int b = 0; b < BB; b++) acc[b] = 0.0f;
#pragma unroll 4
    for (int k = 0; k < 192; k += 4) {
        float4 wv = *(const float4*)(w + k);
#pragma unroll
        for (int b = 0; b < BB; b++)
            acc[b] += wv.x * cl[b][k0 + k] + wv.y * cl[b][k0 + k + 1]
                    + wv.z * cl[b][k0 + k + 2] + wv.w * cl[b][k0 + k + 3];
    }
#pragma unroll
    for (int b = 0; b < BB; b++) red[ks][nl][b] = acc[b];
    __syncthreads();
    if (ks == 0) {
        float bias = db[n];
#pragma unroll
        for (int b = 0; b < BB; b++)
            g_clsw[b * NOUT + n] = red[0][nl][b] + red[1][nl][b] + red[2][nl][b]
                                 + red[3][nl][b] + bias;
    }
}

// ---------------------------------------------------------------------------
// Kernel 2 (FUSED): one CTA per (e, b). Dense fp8 GEMM (4 m-tiles x 6 chunks,
// 2-stage bulk-copy ring) -> bias+RoPE -> bf16 q/k kept in SMEM (8 x 16KB
// dswz blocks: q blocks 0-3, k blocks 4-7) -> 10 upper-tri logits tiles
// straight from SMEM -> masked streaming stores. No global q/k round trip.
// ---------------------------------------------------------------------------
#define NST2 2
#define QK_SMEM (8 * BLKB)                         /* 131072 */
#define DSMEM_FUSED (QK_SMEM + NST2 * 2 * BLKB)    /* 196608 */

__global__ __launch_bounds__(256) void fused_kernel(const float* __restrict__ mask,
                                                    float* __restrict__ out)
{
    extern __shared__ char fsm[];
    const uint32_t sQK   = smem_u32(fsm);
    const uint32_t sStg  = sQK + QK_SMEM;
    __shared__ uint64_t mbv[NST2];
    __shared__ float bias_s[128];
    const uint32_t mb0 = smem_u32(mbv);

    const int e = blockIdx.x;
    const int b = blockIdx.y;
    const int tid = threadIdx.x;
    const int lane = tid & 31;
    const int wid  = tid >> 5;
    const int warpM = wid >> 2;
    const int warpN = wid & 3;

    if (tid < 128) bias_s[tid] = g_clsw[b * NOUT + e * 128 + tid];
    if (tid == 0) {
        mbar_init(mb0, 1);
        mbar_init(mb0 + 8, 1);
    }
    __syncthreads();

    auto issue = [&](int k, int st) {
        int mt = k / 6, ch = k % 6;
        mbar_expect(mb0 + st * 8, 2 * BLKB);
        bulk_cp(sStg + st * 2 * BLKB,
                g_hidden_blk + ((size_t)(b * 4 + mt) * 6 + ch) * BLKB, BLKB, mb0 + st * 8);
        bulk_cp(sStg + st * 2 * BLKB + BLKB,
                g_wbf_blk + ((size_t)e * 6 + ch) * BLKB, BLKB, mb0 + st * 8);
    };
    if (tid == 0) { issue(0, 0); issue(1, 1); }

    const int g = lane >> 2, q = lane & 3;

    float acc[4][4][4];
#pragma unroll
    for (int i = 0; i < 4; i++)
#pragma unroll
        for (int j = 0; j < 4; j++)
#pragma unroll
            for (int r = 0; r < 4; r++) acc[i][j][r] = 0.0f;

    // ---- dense phase: 24 chunk-loads, pipeline continuous across m-tiles ---
    for (int k = 0; k < 24; k++) {
        const int st = k & 1;
        mbar_wait(mb0 + st * 8, (uint32_t)((k >> 1) & 1));

        const uint32_t aS = sStg + st * 2 * BLKB;
        const uint32_t bS = aS + BLKB;
#pragma unroll
        for (int kstep = 0; kstep < 4; kstep++) {
            const int colb = kstep * 32 + (lane >> 4) * 16;
            uint32_t areg[4][4], breg[4][2];
#pragma unroll
            for (int mi = 0; mi < 4; mi++)
                ldsm4(areg[mi], aS + dswz(warpM * 64 + mi * 16 + (lane & 15), colb));
#pragma unroll
            for (int jp = 0; jp < 2; jp++) {
                uint32_t t4[4];
                ldsm4(t4, bS + dswz(warpN * 32 + jp * 16 + (lane & 15), colb));
                breg[jp * 2][0]     = t4[0];
                breg[jp * 2 + 1][0] = t4[1];
                breg[jp * 2][1]     = t4[2];
                breg[jp * 2 + 1][1] = t4[3];
            }
#pragma unroll
            for (int mi = 0; mi < 4; mi++)
#pragma unroll
                for (int j = 0; j < 4; j++)
                    mma16832f8(acc[mi][j], areg[mi], breg[j]);
        }

        if ((k % 6) == 5) {
            // ---- m-tile epilogue: unscale + bias + RoPE -> bf16 SMEM qk ----
            const int mt = k / 6;
#pragma unroll
            for (int mi = 0; mi < 4; mi++) {
#pragma unroll
                for (int h = 0; h < 2; h++) {
                    int row = warpM * 64 + mi * 16 + h * 8 + g;
                    int s = mt * 128 + row;
#pragma unroll
                    for (int j = 0; j < 4; j++) {
                        int c = warpN * 32 + j * 8 + 2 * q;
                        float x = acc[mi][j][h * 2]     * WISCALE + bias_s[c];
                        float y = acc[mi][j][h * 2 + 1] * WISCALE + bias_s[c + 1];
                        int t = (c & 63) >> 1;
                        float2 rc = g_rope[s * 32 + t];
                        float rx = x * rc.x - y * rc.y;
                        float ry = y * rc.x + x * rc.y;
                        __nv_bfloat162 p = __floats2bfloat162_rn(rx, ry);
                        int qk = c >> 6, col = c & 63;
                        uint32_t off = (uint32_t)(qk * 4 + mt) * BLKB
                                     + dswz(row, (col >> 3) << 4) + (col & 7) * 2;
                        *(uint32_t*)(fsm + off) = *(uint32_t*)&p;
                        acc[mi][j][h * 2] = 0.0f;
                        acc[mi][j][h * 2 + 1] = 0.0f;
                    }
                }
            }
        }

        __syncthreads();               // stage st fully consumed (+ epi visible)
        if (tid == 0 && k + 2 < 24) issue(k + 2, st);
    }

    // ---- logits phase: 10 upper-tri tiles from SMEM ------------------------
    const int MTs[10] = {0, 0, 0, 0, 1, 1, 1, 2, 2, 3};
    const int NTs[10] = {0, 1, 2, 3, 1, 2, 3, 2, 3, 3};
    const size_t rowbase = ((size_t)(b * ENT + e)) * SS;

    for (int ti = 0; ti < 10; ti++) {
        const int mt = MTs[ti], nt = NTs[ti];
        const int m0 = mt * 128, n0 = nt * 128;
        const uint32_t sQ = sQK + (uint32_t)mt * BLKB;
        const uint32_t sK = sQK + (uint32_t)(4 + nt) * BLKB;

        float lac[4][4][4];
#pragma unroll
        for (int i = 0; i < 4; i++)
#pragma unroll
            for (int j = 0; j < 4; j++)
#pragma unroll
                for (int r = 0; r < 4; r++) lac[i][j][r] = 0.0f;

#pragma unroll
        for (int kstep = 0; kstep < 4; kstep++) {
            const int colb = kstep * 32 + (lane >> 4) * 16;
            uint32_t areg[4][4], breg[4][2];
#pragma unroll
            for (int mi = 0; mi < 4; mi++)
                ldsm4(areg[mi], sQ + dswz(warpM * 64 + mi * 16 + (lane & 15), colb));
#pragma unroll
            for (int jp = 0; jp < 2; jp++) {
                uint32_t t4[4];
                ldsm4(t4, sK + dswz(warpN * 32 + jp * 16 + (lane & 15), colb));
                breg[jp * 2][0]     = t4[0];
                breg[jp * 2 + 1][0] = t4[1];
                breg[jp * 2][1]     = t4[2];
                breg[jp * 2 + 1][1] = t4[3];
            }
#pragma unroll
            for (int mi = 0; mi < 4; mi++)
#pragma unroll
                for (int j = 0; j < 4; j++)
                    mma16816(lac[mi][j], areg[mi], breg[j]);
        }

        const int nbase = n0 + warpN * 32;
        float p0[4], p1[4];
#pragma unroll
        for (int j = 0; j < 4; j++) {
            int c = nbase + j * 8 + 2 * q;
            p0[j] = mask[b * SS + c];
            p1[j] = mask[b * SS + c + 1];
        }

#pragma unroll
        for (int mi = 0; mi < 4; mi++) {
#pragma unroll
            for (int h = 0; h < 2; h++) {
                int m = m0 + warpM * 64 + mi * 16 + h * 8 + g;
                size_t orow = (rowbase + m) * SS;
#pragma unroll
                for (int j = 0; j < 4; j++) {
                    int c = nbase + j * 8 + 2 * q;
                    float x = lac[mi][j][h * 2];
                    float y = lac[mi][j][h * 2 + 1];
                    x = x * p0[j] - (1.0f - p0[j]) * BIGF;
                    y = y * p1[j] - (1.0f - p1[j]) * BIGF;
                    if (m > c)     x -= BIGF;
                    if (m > c + 1) y -= BIGF;
                    __stcs((float2*)(out + orow + c), make_float2(x * 0.125f, y * 0.125f));
                }
            }
        }
    }
}

// ---------------------------------------------------------------------------
extern "C" void kernel_launch(void* const* d_in, const int* in_sizes, int n_in,
                              void* d_out, int out_size)
{
    const float* lhs    = (const float*)d_in[0];
    const float* cls    = (const float*)d_in[1];
    const float* h0     = (const float*)d_in[2];
    const float* mask   = (const float*)d_in[3];
    const float* w_ih_f = (const float*)d_in[4];
    const float* w_hh_f = (const float*)d_in[5];
    const float* b_ih_f = (const float*)d_in[6];
    const float* b_hh_f = (const float*)d_in[7];
    const float* w_ih_b = (const float*)d_in[8];
    const float* w_hh_b = (const float*)d_in[9];
    const float* b_ih_b = (const float*)d_in[10];
    const float* b_hh_b = (const float*)d_in[11];
    const float* dw     = (const float*)d_in[12];
    const float* db     = (const float*)d_in[13];
    float* out = (float*)d_out;

    cudaFuncSetAttribute(fused_kernel, cudaFuncAttributeMaxDynamicSharedMemorySize,
                         DSMEM_FUSED);

    prep_kernel<<<PREPB, 256>>>(dw, lhs, cls, h0, w_ih_f, w_hh_f, b_ih_f, b_hh_f,
                                w_ih_b, w_hh_b, b_ih_b, b_hh_b, mask, out);
    clsw_kernel<<<NOUT / 64, 256>>>(dw, db);

    fused_kernel<<<dim3(ENT, BB), 256, DSMEM_FUSED>>>(mask, out);
}